// round 2
// baseline (speedup 1.0000x reference)
#include <cuda_runtime.h>
#include <math.h>

#define BSZ 2
#define SEQ 2048
#define NH 16
#define DKV 64
#define DMODEL 1024
#define INNER 1024

// ---------------- scratch (static device memory; no allocations) ----------------
__device__ float g_q[BSZ * NH * SEQ * DKV];     // 16 MB  (b,h,s,d)
__device__ float g_k[BSZ * NH * SEQ * DKV];     // 16 MB
__device__ float g_v[BSZ * NH * SEQ * DKV];     // 16 MB
__device__ float g_ctx[BSZ * SEQ * INNER];      // 16 MB  (b,s,inner)
__device__ float g_bias[NH * 4096];             // rel-pos bias per (h, delta+2047)
__device__ float g_maskf[BSZ * SEQ];            // 0.0f or -inf per (b,k)

// ---------------- mask preprocessing: detect uint8 vs int32 storage ----------------
__global__ void maskprep_kernel(const unsigned char* __restrict__ mraw) {
    __shared__ int s_nonzero;
    const int tid = threadIdx.x;   // 1024 threads, single block
    if (tid == 0) s_nonzero = 0;
    __syncthreads();
    int cnt = 0;
    for (int i = tid; i < BSZ * SEQ; i += 1024)
        if ((i & 3) && mraw[i]) cnt++;
    if (cnt) atomicAdd(&s_nonzero, cnt);
    __syncthreads();
    const bool is_u8 = (s_nonzero > 0);
    const int* mi = (const int*)mraw;
    for (int i = tid; i < BSZ * SEQ; i += 1024) {
        int flag = is_u8 ? (int)mraw[i] : mi[i];
        g_maskf[i] = flag ? -INFINITY : 0.0f;
    }
}

// ---------------- T5 relative-position bucket (matches jax op order) ----------------
__device__ __forceinline__ int rel_bucket(int delta) {
    int ret = (delta > 0) ? 32 : 0;
    int n = (delta < 0) ? -delta : delta;
    if (n < 16) return ret + n;
    float t = logf((float)n / 16.0f);
    t = t / 1.1394342831883648f;   // np.log(50/16), float64 constant as in jax
    t = t * 16.0f;
    int large = 16 + (int)t;       // astype(int32): truncate toward zero
    if (large > 31) large = 31;
    return ret + large;
}

__global__ void biasfill_kernel(const float* __restrict__ rel_table) {
    int idx = blockIdx.x * 256 + threadIdx.x;   // NH*4096 = 65536
    int h = idx >> 12;
    int dd = idx & 4095;
    int delta = dd - (SEQ - 1);
    if (dd >= 2 * SEQ - 1) delta = 0;           // pad slot, never read
    int bucket = rel_bucket(delta);
    g_bias[idx] = rel_table[bucket * NH + h];
}

// pos_bias output: (1, h, q, k) = g_bias[h][k - q + 2047]
__global__ void posbias_kernel(float* __restrict__ pb) {
    size_t idx = (size_t)blockIdx.x * 256 + threadIdx.x;   // NH*SEQ*SEQ
    int k = (int)(idx & (SEQ - 1));
    int q = (int)((idx >> 11) & (SEQ - 1));
    int h = (int)(idx >> 22);
    pb[idx] = g_bias[(h << 12) + (k - q + SEQ - 1)];
}

// ---------------- generic 128x128x8 SGEMM, C = A*B + bias ----------------
// mode 0: C[m*N+n]
// mode 1: projection epilogue -> (b,h,s,d) layout
__global__ __launch_bounds__(256) void sgemm128(
    const float* __restrict__ A, const float* __restrict__ B,
    const float* __restrict__ bias, float* __restrict__ C,
    int M, int N, int K, int mode)
{
    __shared__ float As[8][128];
    __shared__ float Bs[8][128];
    const int tid = threadIdx.x;
    const int m0 = blockIdx.y * 128;
    const int n0 = blockIdx.x * 128;
    const int tr = (tid >> 4) * 8;
    const int tc = (tid & 15) * 8;
    const int ar = tid >> 1;           // 0..127
    const int ac = (tid & 1) * 4;      // 0 / 4
    const int br = tid >> 5;           // 0..7
    const int bc = (tid & 31) * 4;

    float acc[8][8];
#pragma unroll
    for (int i = 0; i < 8; i++)
#pragma unroll
        for (int j = 0; j < 8; j++) acc[i][j] = 0.f;

    for (int k0 = 0; k0 < K; k0 += 8) {
        float4 av = *reinterpret_cast<const float4*>(&A[(size_t)(m0 + ar) * K + k0 + ac]);
        float4 bv = *reinterpret_cast<const float4*>(&B[(size_t)(k0 + br) * N + n0 + bc]);
        __syncthreads();
        As[ac + 0][ar] = av.x; As[ac + 1][ar] = av.y;
        As[ac + 2][ar] = av.z; As[ac + 3][ar] = av.w;
        *reinterpret_cast<float4*>(&Bs[br][bc]) = bv;
        __syncthreads();
#pragma unroll
        for (int kk = 0; kk < 8; kk++) {
            float a[8], b[8];
            *(float4*)&a[0] = *(float4*)&As[kk][tr];
            *(float4*)&a[4] = *(float4*)&As[kk][tr + 4];
            *(float4*)&b[0] = *(float4*)&Bs[kk][tc];
            *(float4*)&b[4] = *(float4*)&Bs[kk][tc + 4];
#pragma unroll
            for (int i = 0; i < 8; i++)
#pragma unroll
                for (int j = 0; j < 8; j++)
                    acc[i][j] = fmaf(a[i], b[j], acc[i][j]);
        }
    }

    if (mode == 0) {
#pragma unroll
        for (int i = 0; i < 8; i++) {
            int m = m0 + tr + i;
#pragma unroll
            for (int j = 0; j < 8; j++) {
                int n = n0 + tc + j;
                C[(size_t)m * N + n] = acc[i][j] + bias[n];
            }
        }
    } else {
#pragma unroll
        for (int i = 0; i < 8; i++) {
            int m = m0 + tr + i;
            int b = m / SEQ, s = m % SEQ;
#pragma unroll
            for (int j = 0; j < 8; j++) {
                int n = n0 + tc + j;
                int h = n >> 6, d = n & 63;
                C[(((size_t)(b * NH + h)) * SEQ + s) * DKV + d] = acc[i][j] + bias[n];
            }
        }
    }
}

// ---------------- scores = Q K^T per (b,h) slab (K-dim = 64, single pass) ----------------
__global__ __launch_bounds__(256) void qk_kernel(float* __restrict__ wts) {
    const int tid = threadIdx.x;
    const int bh = blockIdx.z;
    const int q0 = blockIdx.y * 64;
    const int k0 = blockIdx.x * 64;
    const float* qp = g_q + (size_t)bh * SEQ * DKV;
    const float* kp = g_k + (size_t)bh * SEQ * DKV;
    float* sp = wts + (size_t)bh * SEQ * SEQ;

    __shared__ float Qs[64][68];   // [d][row]
    __shared__ float Ks[64][68];   // [d][col]

#pragma unroll
    for (int it = 0; it < 4; it++) {
        int lin = tid + it * 256;          // float4 index over 64x16
        int row = lin >> 4;
        int d4 = (lin & 15) * 4;
        float4 v = *reinterpret_cast<const float4*>(&qp[(size_t)(q0 + row) * DKV + d4]);
        Qs[d4 + 0][row] = v.x; Qs[d4 + 1][row] = v.y;
        Qs[d4 + 2][row] = v.z; Qs[d4 + 3][row] = v.w;
        float4 w = *reinterpret_cast<const float4*>(&kp[(size_t)(k0 + row) * DKV + d4]);
        Ks[d4 + 0][row] = w.x; Ks[d4 + 1][row] = w.y;
        Ks[d4 + 2][row] = w.z; Ks[d4 + 3][row] = w.w;
    }
    __syncthreads();

    const int tr = (tid >> 4) * 4;
    const int tc = (tid & 15) * 4;
    float acc[4][4] = {};
#pragma unroll
    for (int d = 0; d < 64; d++) {
        float a[4], b[4];
        *(float4*)a = *(float4*)&Qs[d][tr];
        *(float4*)b = *(float4*)&Ks[d][tc];
#pragma unroll
        for (int i = 0; i < 4; i++)
#pragma unroll
            for (int j = 0; j < 4; j++)
                acc[i][j] = fmaf(a[i], b[j], acc[i][j]);
    }
#pragma unroll
    for (int i = 0; i < 4; i++)
#pragma unroll
        for (int j = 0; j < 4; j++)
            sp[(size_t)(q0 + tr + i) * SEQ + k0 + tc + j] = acc[i][j];
}

// ---------------- softmax (in-place on weights region), bias + key-mask fused ----------------
__global__ __launch_bounds__(256) void softmax_kernel(float* __restrict__ wts)
{
    const int row = blockIdx.x;            // (b,h,q) flattened
    const int q = row & (SEQ - 1);
    const int bh = row >> 11;
    const int h = bh & 15, b = bh >> 4;
    float* wp = wts + (size_t)row * SEQ;
    const float* bias_h = g_bias + (h << 12) + (SEQ - 1) - q;  // index by k
    const float* mrow = g_maskf + b * SEQ;
    const int tid = threadIdx.x;

    __shared__ float sm[8], ss[8];
    float v[8];
    float mx = -INFINITY;
#pragma unroll
    for (int i = 0; i < 8; i++) {
        int kk = tid + (i << 8);
        float val = wp[kk] + bias_h[kk] + mrow[kk];
        v[i] = val;
        mx = fmaxf(mx, val);
    }
    for (int o = 16; o; o >>= 1) mx = fmaxf(mx, __shfl_xor_sync(0xffffffffu, mx, o));
    if ((tid & 31) == 0) sm[tid >> 5] = mx;
    __syncthreads();
    mx = sm[0];
#pragma unroll
    for (int w = 1; w < 8; w++) mx = fmaxf(mx, sm[w]);

    float sum = 0.f;
#pragma unroll
    for (int i = 0; i < 8; i++) { v[i] = expf(v[i] - mx); sum += v[i]; }
    for (int o = 16; o; o >>= 1) sum += __shfl_xor_sync(0xffffffffu, sum, o);
    if ((tid & 31) == 0) ss[tid >> 5] = sum;
    __syncthreads();
    sum = 0.f;
#pragma unroll
    for (int w = 0; w < 8; w++) sum += ss[w];
    float inv = 1.0f / sum;
#pragma unroll
    for (int i = 0; i < 8; i++) wp[tid + (i << 8)] = v[i] * inv;
}

// ---------------- context = weights @ V per (b,h), N = 64 ----------------
__global__ __launch_bounds__(256) void wv_kernel(const float* __restrict__ wts) {
    const int tid = threadIdx.x;
    const int bh = blockIdx.z;
    const int b = bh >> 4, h = bh & 15;
    const int m0 = blockIdx.y * 64;
    const float* wp = wts + (size_t)bh * SEQ * SEQ;
    const float* vp = g_v + (size_t)bh * SEQ * DKV;

    __shared__ float Ws[16][68];   // [k][m]
    __shared__ float Vs[16][64];   // [k][n]
    float acc[4][4] = {};
    const int tr = (tid >> 4) * 4;
    const int tc = (tid & 15) * 4;
    const int awr = tid >> 2;            // 0..63
    const int awc = (tid & 3) * 4;       // 0..12
    const int bvr = tid >> 4;            // 0..15
    const int bvc = (tid & 15) * 4;

    for (int k0 = 0; k0 < SEQ; k0 += 16) {
        float4 wv4 = *reinterpret_cast<const float4*>(&wp[(size_t)(m0 + awr) * SEQ + k0 + awc]);
        float4 vv4 = *reinterpret_cast<const float4*>(&vp[(size_t)(k0 + bvr) * DKV + bvc]);
        __syncthreads();
        Ws[awc + 0][awr] = wv4.x; Ws[awc + 1][awr] = wv4.y;
        Ws[awc + 2][awr] = wv4.z; Ws[awc + 3][awr] = wv4.w;
        *reinterpret_cast<float4*>(&Vs[bvr][bvc]) = vv4;
        __syncthreads();
#pragma unroll
        for (int kk = 0; kk < 16; kk++) {
            float a[4], bb[4];
            *(float4*)a = *(float4*)&Ws[kk][tr];
            *(float4*)bb = *(float4*)&Vs[kk][tc];
#pragma unroll
            for (int i = 0; i < 4; i++)
#pragma unroll
                for (int j = 0; j < 4; j++)
                    acc[i][j] = fmaf(a[i], bb[j], acc[i][j]);
        }
    }
#pragma unroll
    for (int i = 0; i < 4; i++)
#pragma unroll
        for (int j = 0; j < 4; j++)
            g_ctx[((size_t)(b * SEQ + m0 + tr + i)) * INNER + h * DKV + tc + j] = acc[i][j];
}

// ---------------- launch ----------------
extern "C" void kernel_launch(void* const* d_in, const int* in_sizes, int n_in,
                              void* d_out, int out_size) {
    const float* x  = (const float*)d_in[0];
    const float* Wq = (const float*)d_in[1];
    const float* bq = (const float*)d_in[2];
    const float* Wk = (const float*)d_in[3];
    const float* bk = (const float*)d_in[4];
    const float* Wv = (const float*)d_in[5];
    const float* bv = (const float*)d_in[6];
    const float* Wo = (const float*)d_in[7];
    const float* bo = (const float*)d_in[8];
    const float* rel_table = (const float*)d_in[9];
    const unsigned char* mask = (const unsigned char*)d_in[10];

    float* out = (float*)d_out;
    float* wts = out + (size_t)BSZ * SEQ * DMODEL;          // (b,h,q,k) weights
    float* pb  = wts + (size_t)BSZ * NH * SEQ * SEQ;        // (1,h,q,k) pos_bias

    float *pq, *pk, *pv, *pctx;
    cudaGetSymbolAddress((void**)&pq,  g_q);
    cudaGetSymbolAddress((void**)&pk,  g_k);
    cudaGetSymbolAddress((void**)&pv,  g_v);
    cudaGetSymbolAddress((void**)&pctx, g_ctx);

    const int M = BSZ * SEQ;   // 4096

    maskprep_kernel<<<1, 1024>>>(mask);
    biasfill_kernel<<<256, 256>>>(rel_table);

    dim3 gproj(INNER / 128, M / 128);
    sgemm128<<<gproj, 256>>>(x, Wq, bq, pq, M, INNER, DMODEL, 1);
    sgemm128<<<gproj, 256>>>(x, Wk, bk, pk, M, INNER, DMODEL, 1);
    sgemm128<<<gproj, 256>>>(x, Wv, bv, pv, M, INNER, DMODEL, 1);

    qk_kernel<<<dim3(SEQ / 64, SEQ / 64, BSZ * NH), 256>>>(wts);

    softmax_kernel<<<BSZ * NH * SEQ, 256>>>(wts);

    posbias_kernel<<<(NH * (size_t)SEQ * SEQ) / 256, 256>>>(pb);

    wv_kernel<<<dim3(1, SEQ / 64, BSZ * NH), 256>>>(wts);

    sgemm128<<<dim3(DMODEL / 128, M / 128), 256>>>(pctx, Wo, bo, out, M, DMODEL, INNER, 0);
}

// round 4
// speedup vs baseline: 1.3258x; 1.3258x over previous
#include <cuda_runtime.h>
#include <cuda_bf16.h>
#include <math.h>
#include <stdint.h>

#define BSZ 2
#define SEQ 2048
#define NH 16
#define DKV 64
#define DMODEL 1024
#define INNER 1024
#define MTOT (BSZ * SEQ)   // 4096

// ---------------- scratch (static device memory; no allocations) ----------------
__device__ float g_q[BSZ * NH * SEQ * DKV];     // (b,h,s,d) f32
__device__ float g_k[BSZ * NH * SEQ * DKV];
__device__ float g_v[BSZ * NH * SEQ * DKV];
__device__ float g_ctx[MTOT * INNER];           // (b,s,inner) f32
__device__ float g_bias[NH * 4096];
__device__ float g_maskf[BSZ * SEQ];
// bf16 hi/lo split operands for tensor-core GEMMs
__device__ __nv_bfloat16 g_xhi[MTOT * DMODEL];
__device__ __nv_bfloat16 g_xlo[MTOT * DMODEL];
__device__ __nv_bfloat16 g_whi[4u * DMODEL * INNER];   // transposed [n][k]; 0=Wq 1=Wk 2=Wv 3=Wo
__device__ __nv_bfloat16 g_wlo[4u * DMODEL * INNER];
__device__ __nv_bfloat16 g_chi[MTOT * INNER];
__device__ __nv_bfloat16 g_clo[MTOT * INNER];

// ---------------- PTX helpers ----------------
__device__ __forceinline__ uint32_t smem_u32(const void* p) {
    uint32_t a;
    asm("{ .reg .u64 t; cvta.to.shared.u64 t, %1; cvt.u32.u64 %0, t; }" : "=r"(a) : "l"(p));
    return a;
}

#define LDSM_X4(r0, r1, r2, r3, addr) \
    asm volatile("ldmatrix.sync.aligned.m8n8.x4.shared.b16 {%0,%1,%2,%3}, [%4];" \
                 : "=r"(r0), "=r"(r1), "=r"(r2), "=r"(r3) : "r"(addr))
#define LDSM_X2(r0, r1, addr) \
    asm volatile("ldmatrix.sync.aligned.m8n8.x2.shared.b16 {%0,%1}, [%2];" \
                 : "=r"(r0), "=r"(r1) : "r"(addr))

__device__ __forceinline__ void mma16816(float* c, const uint32_t* a, const uint32_t* b) {
    asm volatile("mma.sync.aligned.m16n8k16.row.col.f32.bf16.bf16.f32 "
                 "{%0,%1,%2,%3}, {%4,%5,%6,%7}, {%8,%9}, {%0,%1,%2,%3};"
                 : "+f"(c[0]), "+f"(c[1]), "+f"(c[2]), "+f"(c[3])
                 : "r"(a[0]), "r"(a[1]), "r"(a[2]), "r"(a[3]), "r"(b[0]), "r"(b[1]));
}

// ---------------- mask preprocessing (bool stored as int32) ----------------
__global__ void maskprep_kernel(const unsigned char* __restrict__ mraw) {
    __shared__ int s_nonzero;
    const int tid = threadIdx.x;
    if (tid == 0) s_nonzero = 0;
    __syncthreads();
    int cnt = 0;
    for (int i = tid; i < BSZ * SEQ; i += 1024)
        if ((i & 3) && mraw[i]) cnt++;
    if (cnt) atomicAdd(&s_nonzero, cnt);
    __syncthreads();
    const bool is_u8 = (s_nonzero > 0);
    const int* mi = (const int*)mraw;
    for (int i = tid; i < BSZ * SEQ; i += 1024) {
        int flag = is_u8 ? (int)mraw[i] : mi[i];
        g_maskf[i] = flag ? -INFINITY : 0.0f;
    }
}

// ---------------- T5 relative-position bucket ----------------
__device__ __forceinline__ int rel_bucket(int delta) {
    int ret = (delta > 0) ? 32 : 0;
    int n = (delta < 0) ? -delta : delta;
    if (n < 16) return ret + n;
    float t = logf((float)n / 16.0f);
    t = t / 1.1394342831883648f;
    t = t * 16.0f;
    int large = 16 + (int)t;
    if (large > 31) large = 31;
    return ret + large;
}

__global__ void biasfill_kernel(const float* __restrict__ rel_table) {
    int idx = blockIdx.x * 256 + threadIdx.x;
    int h = idx >> 12;
    int dd = idx & 4095;
    int delta = dd - (SEQ - 1);
    if (dd >= 2 * SEQ - 1) delta = 0;
    g_bias[idx] = rel_table[rel_bucket(delta) * NH + h];
}

// ---------------- f32 -> bf16 hi/lo split ----------------
__global__ void cvt_split_kernel(const float* __restrict__ src,
                                 __nv_bfloat16* __restrict__ dhi,
                                 __nv_bfloat16* __restrict__ dlo) {
    size_t i = ((size_t)blockIdx.x * 256 + threadIdx.x) * 4;
    float4 v = *(const float4*)(src + i);
    float f[4] = {v.x, v.y, v.z, v.w};
    unsigned short hs[4], ls[4];
#pragma unroll
    for (int j = 0; j < 4; j++) {
        __nv_bfloat16 h = __float2bfloat16(f[j]);
        hs[j] = __bfloat16_as_ushort(h);
        ls[j] = __bfloat16_as_ushort(__float2bfloat16(f[j] - __bfloat162float(h)));
    }
    uint2 H, L;
    H.x = (uint32_t)hs[0] | ((uint32_t)hs[1] << 16);
    H.y = (uint32_t)hs[2] | ((uint32_t)hs[3] << 16);
    L.x = (uint32_t)ls[0] | ((uint32_t)ls[1] << 16);
    L.y = (uint32_t)ls[2] | ((uint32_t)ls[3] << 16);
    *(uint2*)(dhi + i) = H;
    *(uint2*)(dlo + i) = L;
}

// ---------------- W [K][N] f32 -> Wt [N][K] bf16 hi/lo ----------------
__global__ void transpose_split_kernel(const float* __restrict__ src,
                                       __nv_bfloat16* __restrict__ dhi,
                                       __nv_bfloat16* __restrict__ dlo) {
    __shared__ float t[32][33];
    int tx = threadIdx.x & 31, ty = threadIdx.x >> 5;
    int n0 = blockIdx.x * 32, k0 = blockIdx.y * 32;
#pragma unroll
    for (int j = 0; j < 32; j += 8)
        t[ty + j][tx] = src[(size_t)(k0 + ty + j) * INNER + n0 + tx];
    __syncthreads();
#pragma unroll
    for (int j = 0; j < 32; j += 8) {
        float v = t[tx][ty + j];
        int n = n0 + ty + j, k = k0 + tx;
        __nv_bfloat16 h = __float2bfloat16(v);
        dhi[(size_t)n * DMODEL + k] = h;
        dlo[(size_t)n * DMODEL + k] = __float2bfloat16(v - __bfloat162float(h));
    }
}

// ---------------- mma.sync bf16 hi/lo GEMM: C[4096 x 1024] = A * B^T + bias ----------------
// A: [4096][1024] bf16 hi/lo.  B: [1024][1024] bf16 hi/lo, K-major (pre-transposed [n][k]).
// Block 128(m) x 64(n), 8 warps, each warp 32x32. K-chunk 32.
// mode 0: flat C.  mode 1: QKV epilogue -> (b,h,s,d)
#define APAD 40   // row stride in bf16 elems (32 data + 8 pad = 80B)

__global__ __launch_bounds__(256) void mma_gemm_kernel(
    const __nv_bfloat16* __restrict__ Ahi, const __nv_bfloat16* __restrict__ Alo,
    const __nv_bfloat16* __restrict__ Bhi, const __nv_bfloat16* __restrict__ Blo,
    const float* __restrict__ bias, float* __restrict__ C, int mode)
{
    __shared__ __nv_bfloat16 sA[2][128][APAD];   // 20480 B
    __shared__ __nv_bfloat16 sB[2][64][APAD];    // 10240 B

    const int tid = threadIdx.x;
    const int wid = tid >> 5, lane = tid & 31;
    const int m0 = blockIdx.y * 128;
    const int n0b = blockIdx.x * 64;
    const int mw = (wid & 3) * 32;
    const int nw = (wid >> 2) * 32;

    float acc[2][4][4];
#pragma unroll
    for (int mt = 0; mt < 2; mt++)
#pragma unroll
        for (int nt = 0; nt < 4; nt++)
#pragma unroll
            for (int i = 0; i < 4; i++) acc[mt][nt][i] = 0.f;

    const int arow = lane & 15;
    const int acol0 = (lane >> 4) << 3;
    const int brow = lane & 7;
    const int bcol0 = ((lane >> 3) & 1) << 3;

    for (int k0 = 0; k0 < 1024; k0 += 32) {
        __syncthreads();
#pragma unroll
        for (int h = 0; h < 2; h++) {
            const __nv_bfloat16* as = h ? Alo : Ahi;
#pragma unroll
            for (int it = 0; it < 2; it++) {
                int idx = tid + it * 256;              // 0..511
                int r = idx >> 2, seg = idx & 3;
                uint4 v = *(const uint4*)(as + (size_t)(m0 + r) * 1024 + k0 + seg * 8);
                *(uint4*)&sA[h][r][seg * 8] = v;
            }
            const __nv_bfloat16* bs = h ? Blo : Bhi;
            {
                int r = tid >> 2, seg = tid & 3;
                uint4 v = *(const uint4*)(bs + (size_t)(n0b + r) * 1024 + k0 + seg * 8);
                *(uint4*)&sB[h][r][seg * 8] = v;
            }
        }
        __syncthreads();

#pragma unroll
        for (int kk = 0; kk < 32; kk += 16) {
            uint32_t aHi[2][4], aLo[2][4], bHi[4][2], bLo[4][2];
#pragma unroll
            for (int mt = 0; mt < 2; mt++) {
                uint32_t ah = smem_u32(&sA[0][mw + mt * 16 + arow][kk + acol0]);
                LDSM_X4(aHi[mt][0], aHi[mt][1], aHi[mt][2], aHi[mt][3], ah);
                uint32_t al = smem_u32(&sA[1][mw + mt * 16 + arow][kk + acol0]);
                LDSM_X4(aLo[mt][0], aLo[mt][1], aLo[mt][2], aLo[mt][3], al);
            }
#pragma unroll
            for (int nt = 0; nt < 4; nt++) {
                uint32_t bh = smem_u32(&sB[0][nw + nt * 8 + brow][kk + bcol0]);
                LDSM_X2(bHi[nt][0], bHi[nt][1], bh);
                uint32_t bl = smem_u32(&sB[1][nw + nt * 8 + brow][kk + bcol0]);
                LDSM_X2(bLo[nt][0], bLo[nt][1], bl);
            }
#pragma unroll
            for (int mt = 0; mt < 2; mt++)
#pragma unroll
                for (int nt = 0; nt < 4; nt++) {
                    mma16816(acc[mt][nt], aHi[mt], bHi[nt]);
                    mma16816(acc[mt][nt], aHi[mt], bLo[nt]);
                    mma16816(acc[mt][nt], aLo[mt], bHi[nt]);
                }
        }
    }

    // epilogue: c0,c1 -> (r, c),(r,c+1); c2,c3 -> (r+8, c),(r+8,c+1)
#pragma unroll
    for (int mt = 0; mt < 2; mt++) {
        int r = m0 + mw + mt * 16 + (lane >> 2);
#pragma unroll
        for (int nt = 0; nt < 4; nt++) {
            int n = n0b + nw + nt * 8 + (lane & 3) * 2;
            float2 lo = make_float2(acc[mt][nt][0] + bias[n], acc[mt][nt][1] + bias[n + 1]);
            float2 hi = make_float2(acc[mt][nt][2] + bias[n], acc[mt][nt][3] + bias[n + 1]);
            if (mode == 0) {
                *(float2*)&C[(size_t)r * 1024 + n] = lo;
                *(float2*)&C[(size_t)(r + 8) * 1024 + n] = hi;
            } else {
                int h = n >> 6, d = n & 63;
                int b = r >> 11, s = r & (SEQ - 1);
                *(float2*)&C[(((size_t)(b * NH + h)) * SEQ + s) * DKV + d] = lo;
                int b2 = (r + 8) >> 11, s2 = (r + 8) & (SEQ - 1);
                *(float2*)&C[(((size_t)(b2 * NH + h)) * SEQ + s2) * DKV + d] = hi;
            }
        }
    }
}

// ---------------- scores = Q K^T per (b,h) slab ----------------
__global__ __launch_bounds__(256) void qk_kernel(float* __restrict__ wts) {
    const int tid = threadIdx.x;
    const int bh = blockIdx.z;
    const int q0 = blockIdx.y * 64;
    const int k0 = blockIdx.x * 64;
    const float* qp = g_q + (size_t)bh * SEQ * DKV;
    const float* kp = g_k + (size_t)bh * SEQ * DKV;
    float* sp = wts + (size_t)bh * SEQ * SEQ;

    __shared__ float Qs[64][68];
    __shared__ float Ks[64][68];

#pragma unroll
    for (int it = 0; it < 4; it++) {
        int lin = tid + it * 256;
        int row = lin >> 4;
        int d4 = (lin & 15) * 4;
        float4 v = *reinterpret_cast<const float4*>(&qp[(size_t)(q0 + row) * DKV + d4]);
        Qs[d4 + 0][row] = v.x; Qs[d4 + 1][row] = v.y;
        Qs[d4 + 2][row] = v.z; Qs[d4 + 3][row] = v.w;
        float4 w = *reinterpret_cast<const float4*>(&kp[(size_t)(k0 + row) * DKV + d4]);
        Ks[d4 + 0][row] = w.x; Ks[d4 + 1][row] = w.y;
        Ks[d4 + 2][row] = w.z; Ks[d4 + 3][row] = w.w;
    }
    __syncthreads();

    const int tr = (tid >> 4) * 4;
    const int tc = (tid & 15) * 4;
    float acc[4][4] = {};
#pragma unroll
    for (int d = 0; d < 64; d++) {
        float a[4], b[4];
        *(float4*)a = *(float4*)&Qs[d][tr];
        *(float4*)b = *(float4*)&Ks[d][tc];
#pragma unroll
        for (int i = 0; i < 4; i++)
#pragma unroll
            for (int j = 0; j < 4; j++)
                acc[i][j] = fmaf(a[i], b[j], acc[i][j]);
    }
#pragma unroll
    for (int i = 0; i < 4; i++)
#pragma unroll
        for (int j = 0; j < 4; j++)
            sp[(size_t)(q0 + tr + i) * SEQ + k0 + tc + j] = acc[i][j];
}

// ---------------- softmax in-place; emits pos_bias output from b==0 blocks ----------------
__global__ __launch_bounds__(256) void softmax_kernel(float* __restrict__ wts,
                                                      float* __restrict__ pb)
{
    const int row = blockIdx.x;            // (b,h,q)
    const int q = row & (SEQ - 1);
    const int bh = row >> 11;
    const int h = bh & 15, b = bh >> 4;
    float* wp = wts + (size_t)row * SEQ;
    const float* bias_h = g_bias + (h << 12) + (SEQ - 1) - q;
    const float* mrow = g_maskf + b * SEQ;
    float* pbrow = pb + ((size_t)(h * SEQ + q)) * SEQ;
    const int tid = threadIdx.x;

    __shared__ float sm[8], ss[8];
    float v[8];
    float mx = -INFINITY;
#pragma unroll
    for (int i = 0; i < 8; i++) {
        int kk = tid + (i << 8);
        float bv = bias_h[kk];
        if (b == 0) pbrow[kk] = bv;
        float val = wp[kk] + bv + mrow[kk];
        v[i] = val;
        mx = fmaxf(mx, val);
    }
    for (int o = 16; o; o >>= 1) mx = fmaxf(mx, __shfl_xor_sync(0xffffffffu, mx, o));
    if ((tid & 31) == 0) sm[tid >> 5] = mx;
    __syncthreads();
    mx = sm[0];
#pragma unroll
    for (int w = 1; w < 8; w++) mx = fmaxf(mx, sm[w]);

    float sum = 0.f;
#pragma unroll
    for (int i = 0; i < 8; i++) { v[i] = expf(v[i] - mx); sum += v[i]; }
    for (int o = 16; o; o >>= 1) sum += __shfl_xor_sync(0xffffffffu, sum, o);
    if ((tid & 31) == 0) ss[tid >> 5] = sum;
    __syncthreads();
    sum = 0.f;
#pragma unroll
    for (int w = 0; w < 8; w++) sum += ss[w];
    float inv = 1.0f / sum;
#pragma unroll
    for (int i = 0; i < 8; i++) wp[tid + (i << 8)] = v[i] * inv;
}

// ---------------- context = weights @ V per (b,h) ----------------
__global__ __launch_bounds__(256) void wv_kernel(const float* __restrict__ wts) {
    const int tid = threadIdx.x;
    const int bh = blockIdx.z;
    const int b = bh >> 4, h = bh & 15;
    const int m0 = blockIdx.y * 64;
    const float* wp = wts + (size_t)bh * SEQ * SEQ;
    const float* vp = g_v + (size_t)bh * SEQ * DKV;

    __shared__ float Ws[16][68];
    __shared__ float Vs[16][64];
    float acc[4][4] = {};
    const int tr = (tid >> 4) * 4;
    const int tc = (tid & 15) * 4;
    const int awr = tid >> 2;
    const int awc = (tid & 3) * 4;
    const int bvr = tid >> 4;
    const int bvc = (tid & 15) * 4;

    for (int k0 = 0; k0 < SEQ; k0 += 16) {
        float4 wv4 = *reinterpret_cast<const float4*>(&wp[(size_t)(m0 + awr) * SEQ + k0 + awc]);
        float4 vv4 = *reinterpret_cast<const float4*>(&vp[(size_t)(k0 + bvr) * DKV + bvc]);
        __syncthreads();
        Ws[awc + 0][awr] = wv4.x; Ws[awc + 1][awr] = wv4.y;
        Ws[awc + 2][awr] = wv4.z; Ws[awc + 3][awr] = wv4.w;
        *reinterpret_cast<float4*>(&Vs[bvr][bvc]) = vv4;
        __syncthreads();
#pragma unroll
        for (int kk = 0; kk < 16; kk++) {
            float a[4], bb[4];
            *(float4*)a = *(float4*)&Ws[kk][tr];
            *(float4*)bb = *(float4*)&Vs[kk][tc];
#pragma unroll
            for (int i = 0; i < 4; i++)
#pragma unroll
                for (int j = 0; j < 4; j++)
                    acc[i][j] = fmaf(a[i], bb[j], acc[i][j]);
        }
    }
#pragma unroll
    for (int i = 0; i < 4; i++)
#pragma unroll
        for (int j = 0; j < 4; j++)
            g_ctx[((size_t)(b * SEQ + m0 + tr + i)) * INNER + h * DKV + tc + j] = acc[i][j];
}

// ---------------- launch ----------------
extern "C" void kernel_launch(void* const* d_in, const int* in_sizes, int n_in,
                              void* d_out, int out_size) {
    const float* x  = (const float*)d_in[0];
    const float* Wq = (const float*)d_in[1];
    const float* bq = (const float*)d_in[2];
    const float* Wk = (const float*)d_in[3];
    const float* bk = (const float*)d_in[4];
    const float* Wv = (const float*)d_in[5];
    const float* bv = (const float*)d_in[6];
    const float* Wo = (const float*)d_in[7];
    const float* bo = (const float*)d_in[8];
    const float* rel_table = (const float*)d_in[9];
    const unsigned char* mask = (const unsigned char*)d_in[10];

    float* out = (float*)d_out;
    float* wts = out + (size_t)BSZ * SEQ * DMODEL;
    float* pb  = wts + (size_t)BSZ * NH * SEQ * SEQ;

    float *pq, *pk, *pv, *pctx;
    __nv_bfloat16 *pxhi, *pxlo, *pwhi, *pwlo, *pchi, *pclo;
    cudaGetSymbolAddress((void**)&pq,  g_q);
    cudaGetSymbolAddress((void**)&pk,  g_k);
    cudaGetSymbolAddress((void**)&pv,  g_v);
    cudaGetSymbolAddress((void**)&pctx, g_ctx);
    cudaGetSymbolAddress((void**)&pxhi, g_xhi);
    cudaGetSymbolAddress((void**)&pxlo, g_xlo);
    cudaGetSymbolAddress((void**)&pwhi, g_whi);
    cudaGetSymbolAddress((void**)&pwlo, g_wlo);
    cudaGetSymbolAddress((void**)&pchi, g_chi);
    cudaGetSymbolAddress((void**)&pclo, g_clo);

    const size_t WSTRIDE = (size_t)DMODEL * INNER;

    maskprep_kernel<<<1, 1024>>>(mask);
    biasfill_kernel<<<256, 256>>>(rel_table);

    cvt_split_kernel<<<(MTOT * DMODEL) / 1024, 256>>>(x, pxhi, pxlo);
    dim3 tg(32, 32);
    transpose_split_kernel<<<tg, 256>>>(Wq, pwhi + 0 * WSTRIDE, pwlo + 0 * WSTRIDE);
    transpose_split_kernel<<<tg, 256>>>(Wk, pwhi + 1 * WSTRIDE, pwlo + 1 * WSTRIDE);
    transpose_split_kernel<<<tg, 256>>>(Wv, pwhi + 2 * WSTRIDE, pwlo + 2 * WSTRIDE);
    transpose_split_kernel<<<tg, 256>>>(Wo, pwhi + 3 * WSTRIDE, pwlo + 3 * WSTRIDE);

    dim3 gg(INNER / 64, MTOT / 128);   // (16, 32)
    mma_gemm_kernel<<<gg, 256>>>(pxhi, pxlo, pwhi + 0 * WSTRIDE, pwlo + 0 * WSTRIDE, bq, pq, 1);
    mma_gemm_kernel<<<gg, 256>>>(pxhi, pxlo, pwhi + 1 * WSTRIDE, pwlo + 1 * WSTRIDE, bk, pk, 1);
    mma_gemm_kernel<<<gg, 256>>>(pxhi, pxlo, pwhi + 2 * WSTRIDE, pwlo + 2 * WSTRIDE, bv, pv, 1);

    qk_kernel<<<dim3(SEQ / 64, SEQ / 64, BSZ * NH), 256>>>(wts);

    softmax_kernel<<<BSZ * NH * SEQ, 256>>>(wts, pb);

    wv_kernel<<<dim3(1, SEQ / 64, BSZ * NH), 256>>>(wts);

    cvt_split_kernel<<<(MTOT * INNER) / 1024, 256>>>(pctx, pchi, pclo);
    mma_gemm_kernel<<<gg, 256>>>(pchi, pclo, pwhi + 3 * WSTRIDE, pwlo + 3 * WSTRIDE, bo, out, 0);
}

// round 6
// speedup vs baseline: 1.8615x; 1.4041x over previous
#include <cuda_runtime.h>
#include <cuda_bf16.h>
#include <math.h>
#include <stdint.h>

#define BSZ 2
#define SEQ 2048
#define NH 16
#define DKV 64
#define DMODEL 1024
#define INNER 1024
#define MTOT (BSZ * SEQ)   // 4096

// ---------------- scratch (static device memory; no allocations) ----------------
__device__ float g_bias[NH * 4096];
__device__ float g_maskf[BSZ * SEQ];
__device__ __nv_bfloat16 g_xhi[MTOT * DMODEL];
__device__ __nv_bfloat16 g_xlo[MTOT * DMODEL];
__device__ __nv_bfloat16 g_whi[4u * DMODEL * INNER];   // [n][k]; 0=Wq 1=Wk 2=Wv 3=Wo
__device__ __nv_bfloat16 g_wlo[4u * DMODEL * INNER];
__device__ __nv_bfloat16 g_qhi[BSZ * NH * SEQ * DKV];  // (b,h,s,d)
__device__ __nv_bfloat16 g_qlo[BSZ * NH * SEQ * DKV];
__device__ __nv_bfloat16 g_khi[BSZ * NH * SEQ * DKV];
__device__ __nv_bfloat16 g_klo[BSZ * NH * SEQ * DKV];
__device__ __nv_bfloat16 g_vhi[BSZ * NH * SEQ * DKV];
__device__ __nv_bfloat16 g_vlo[BSZ * NH * SEQ * DKV];
__device__ __nv_bfloat16 g_vthi[BSZ * NH * DKV * SEQ]; // (b,h,d,s)
__device__ __nv_bfloat16 g_vtlo[BSZ * NH * DKV * SEQ];
__device__ __nv_bfloat16 g_chi[MTOT * INNER];          // (b,s,inner)
__device__ __nv_bfloat16 g_clo[MTOT * INNER];

// ---------------- PTX helpers ----------------
__device__ __forceinline__ uint32_t smem_u32(const void* p) {
    uint32_t a;
    asm("{ .reg .u64 t; cvta.to.shared.u64 t, %1; cvt.u32.u64 %0, t; }" : "=r"(a) : "l"(p));
    return a;
}
#define LDSM_X4(r0, r1, r2, r3, addr) \
    asm volatile("ldmatrix.sync.aligned.m8n8.x4.shared.b16 {%0,%1,%2,%3}, [%4];" \
                 : "=r"(r0), "=r"(r1), "=r"(r2), "=r"(r3) : "r"(addr))
#define LDSM_X2(r0, r1, addr) \
    asm volatile("ldmatrix.sync.aligned.m8n8.x2.shared.b16 {%0,%1}, [%2];" \
                 : "=r"(r0), "=r"(r1) : "r"(addr))

__device__ __forceinline__ void mma16816(float* c, const uint32_t* a, const uint32_t* b) {
    asm volatile("mma.sync.aligned.m16n8k16.row.col.f32.bf16.bf16.f32 "
                 "{%0,%1,%2,%3}, {%4,%5,%6,%7}, {%8,%9}, {%0,%1,%2,%3};"
                 : "+f"(c[0]), "+f"(c[1]), "+f"(c[2]), "+f"(c[3])
                 : "r"(a[0]), "r"(a[1]), "r"(a[2]), "r"(a[3]), "r"(b[0]), "r"(b[1]));
}

// split two f32 into packed bf16x2 hi and lo words
__device__ __forceinline__ void split2(float v0, float v1, uint32_t& hi, uint32_t& lo) {
    __nv_bfloat16 h0 = __float2bfloat16(v0), h1 = __float2bfloat16(v1);
    __nv_bfloat16 l0 = __float2bfloat16(v0 - __bfloat162float(h0));
    __nv_bfloat16 l1 = __float2bfloat16(v1 - __bfloat162float(h1));
    hi = (uint32_t)__bfloat16_as_ushort(h0) | ((uint32_t)__bfloat16_as_ushort(h1) << 16);
    lo = (uint32_t)__bfloat16_as_ushort(l0) | ((uint32_t)__bfloat16_as_ushort(l1) << 16);
}

// ---------------- mask preprocessing (bool stored as int32) ----------------
__global__ void maskprep_kernel(const unsigned char* __restrict__ mraw) {
    __shared__ int s_nonzero;
    const int tid = threadIdx.x;
    if (tid == 0) s_nonzero = 0;
    __syncthreads();
    int cnt = 0;
    for (int i = tid; i < BSZ * SEQ; i += 1024)
        if ((i & 3) && mraw[i]) cnt++;
    if (cnt) atomicAdd(&s_nonzero, cnt);
    __syncthreads();
    const bool is_u8 = (s_nonzero > 0);
    const int* mi = (const int*)mraw;
    for (int i = tid; i < BSZ * SEQ; i += 1024) {
        int flag = is_u8 ? (int)mraw[i] : mi[i];
        g_maskf[i] = flag ? -INFINITY : 0.0f;
    }
}

// ---------------- T5 relative-position bucket ----------------
__device__ __forceinline__ int rel_bucket(int delta) {
    int ret = (delta > 0) ? 32 : 0;
    int n = (delta < 0) ? -delta : delta;
    if (n < 16) return ret + n;
    float t = logf((float)n / 16.0f);
    t = t / 1.1394342831883648f;
    t = t * 16.0f;
    int large = 16 + (int)t;
    if (large > 31) large = 31;
    return ret + large;
}

__global__ void biasfill_kernel(const float* __restrict__ rel_table) {
    int idx = blockIdx.x * 256 + threadIdx.x;
    int h = idx >> 12;
    int dd = idx & 4095;
    int delta = dd - (SEQ - 1);
    if (dd >= 2 * SEQ - 1) delta = 0;
    g_bias[idx] = rel_table[rel_bucket(delta) * NH + h];
}

// ---------------- f32 -> bf16 hi/lo split ----------------
__global__ void cvt_split_kernel(const float* __restrict__ src,
                                 __nv_bfloat16* __restrict__ dhi,
                                 __nv_bfloat16* __restrict__ dlo) {
    size_t i = ((size_t)blockIdx.x * 256 + threadIdx.x) * 4;
    float4 v = *(const float4*)(src + i);
    uint2 H, L;
    split2(v.x, v.y, H.x, L.x);
    split2(v.z, v.w, H.y, L.y);
    *(uint2*)(dhi + i) = H;
    *(uint2*)(dlo + i) = L;
}

// ---------------- W [K][N] f32 -> Wt [N][K] bf16 hi/lo ----------------
__global__ void transpose_split_kernel(const float* __restrict__ src,
                                       __nv_bfloat16* __restrict__ dhi,
                                       __nv_bfloat16* __restrict__ dlo) {
    __shared__ float t[32][33];
    int tx = threadIdx.x & 31, ty = threadIdx.x >> 5;
    int n0 = blockIdx.x * 32, k0 = blockIdx.y * 32;
#pragma unroll
    for (int j = 0; j < 32; j += 8)
        t[ty + j][tx] = src[(size_t)(k0 + ty + j) * INNER + n0 + tx];
    __syncthreads();
#pragma unroll
    for (int j = 0; j < 32; j += 8) {
        float v = t[tx][ty + j];
        int n = n0 + ty + j, k = k0 + tx;
        __nv_bfloat16 h = __float2bfloat16(v);
        dhi[(size_t)n * DMODEL + k] = h;
        dlo[(size_t)n * DMODEL + k] = __float2bfloat16(v - __bfloat162float(h));
    }
}

// ---------------- V (b,h,s,d) -> Vt (b,h,d,s), bf16 hi+lo ----------------
__global__ void vtrans_kernel() {
    __shared__ unsigned short th[32][33], tl[32][33];
    const int tx = threadIdx.x & 31, ty = threadIdx.x >> 5;
    const int s0 = blockIdx.x * 32, d0 = blockIdx.y * 32, bh = blockIdx.z;
    const size_t base = (size_t)bh * SEQ * DKV;
#pragma unroll
    for (int j = 0; j < 32; j += 8) {
        size_t o = base + (size_t)(s0 + ty + j) * DKV + d0 + tx;
        th[ty + j][tx] = __bfloat16_as_ushort(g_vhi[o]);
        tl[ty + j][tx] = __bfloat16_as_ushort(g_vlo[o]);
    }
    __syncthreads();
#pragma unroll
    for (int j = 0; j < 32; j += 8) {
        size_t o = base + (size_t)(d0 + ty + j) * SEQ + s0 + tx;
        g_vthi[o] = __ushort_as_bfloat16(th[tx][ty + j]);
        g_vtlo[o] = __ushort_as_bfloat16(tl[tx][ty + j]);
    }
}

// ---------------- mma.sync bf16 hi/lo GEMM: [4096 x 1024] = A * B^T + bias ----------------
// mode 0: flat f32 C.  mode 1: (b,h,s,d) bf16 hi/lo -> Chi/Clo
#define APAD 40

__global__ __launch_bounds__(256) void mma_gemm_kernel(
    const __nv_bfloat16* __restrict__ Ahi, const __nv_bfloat16* __restrict__ Alo,
    const __nv_bfloat16* __restrict__ Bhi, const __nv_bfloat16* __restrict__ Blo,
    const float* __restrict__ bias, float* __restrict__ C,
    __nv_bfloat16* __restrict__ Chi, __nv_bfloat16* __restrict__ Clo, int mode)
{
    __shared__ __nv_bfloat16 sA[2][128][APAD];
    __shared__ __nv_bfloat16 sB[2][64][APAD];

    const int tid = threadIdx.x;
    const int wid = tid >> 5, lane = tid & 31;
    const int m0 = blockIdx.y * 128;
    const int n0b = blockIdx.x * 64;
    const int mw = (wid & 3) * 32;
    const int nw = (wid >> 2) * 32;

    float acc[2][4][4];
#pragma unroll
    for (int mt = 0; mt < 2; mt++)
#pragma unroll
        for (int nt = 0; nt < 4; nt++)
#pragma unroll
            for (int i = 0; i < 4; i++) acc[mt][nt][i] = 0.f;

    const int arow = lane & 15;
    const int acol0 = (lane >> 4) << 3;
    const int brow = lane & 7;
    const int bcol0 = ((lane >> 3) & 1) << 3;

    for (int k0 = 0; k0 < 1024; k0 += 32) {
        __syncthreads();
#pragma unroll
        for (int h = 0; h < 2; h++) {
            const __nv_bfloat16* as = h ? Alo : Ahi;
#pragma unroll
            for (int it = 0; it < 2; it++) {
                int idx = tid + it * 256;
                int r = idx >> 2, seg = idx & 3;
                uint4 v = *(const uint4*)(as + (size_t)(m0 + r) * 1024 + k0 + seg * 8);
                *(uint4*)&sA[h][r][seg * 8] = v;
            }
            const __nv_bfloat16* bs = h ? Blo : Bhi;
            {
                int r = tid >> 2, seg = tid & 3;
                uint4 v = *(const uint4*)(bs + (size_t)(n0b + r) * 1024 + k0 + seg * 8);
                *(uint4*)&sB[h][r][seg * 8] = v;
            }
        }
        __syncthreads();

#pragma unroll
        for (int kk = 0; kk < 32; kk += 16) {
            uint32_t aHi[2][4], aLo[2][4], bHi[4][2], bLo[4][2];
#pragma unroll
            for (int mt = 0; mt < 2; mt++) {
                uint32_t ah = smem_u32(&sA[0][mw + mt * 16 + arow][kk + acol0]);
                LDSM_X4(aHi[mt][0], aHi[mt][1], aHi[mt][2], aHi[mt][3], ah);
                uint32_t al = smem_u32(&sA[1][mw + mt * 16 + arow][kk + acol0]);
                LDSM_X4(aLo[mt][0], aLo[mt][1], aLo[mt][2], aLo[mt][3], al);
            }
#pragma unroll
            for (int nt = 0; nt < 4; nt++) {
                uint32_t bh = smem_u32(&sB[0][nw + nt * 8 + brow][kk + bcol0]);
                LDSM_X2(bHi[nt][0], bHi[nt][1], bh);
                uint32_t bl = smem_u32(&sB[1][nw + nt * 8 + brow][kk + bcol0]);
                LDSM_X2(bLo[nt][0], bLo[nt][1], bl);
            }
#pragma unroll
            for (int mt = 0; mt < 2; mt++)
#pragma unroll
                for (int nt = 0; nt < 4; nt++) {
                    mma16816(acc[mt][nt], aHi[mt], bHi[nt]);
                    mma16816(acc[mt][nt], aHi[mt], bLo[nt]);
                    mma16816(acc[mt][nt], aLo[mt], bHi[nt]);
                }
        }
    }

#pragma unroll
    for (int mt = 0; mt < 2; mt++) {
        int r = m0 + mw + mt * 16 + (lane >> 2);
#pragma unroll
        for (int nt = 0; nt < 4; nt++) {
            int n = n0b + nw + nt * 8 + (lane & 3) * 2;
            float v0 = acc[mt][nt][0] + bias[n], v1 = acc[mt][nt][1] + bias[n + 1];
            float v2 = acc[mt][nt][2] + bias[n], v3 = acc[mt][nt][3] + bias[n + 1];
            if (mode == 0) {
                *(float2*)&C[(size_t)r * 1024 + n] = make_float2(v0, v1);
                *(float2*)&C[(size_t)(r + 8) * 1024 + n] = make_float2(v2, v3);
            } else {
                int h = n >> 6, d = n & 63;
                int b = r >> 11, s = r & (SEQ - 1);
                size_t o1 = (((size_t)(b * NH + h)) * SEQ + s) * DKV + d;
                int b2 = (r + 8) >> 11, s2 = (r + 8) & (SEQ - 1);
                size_t o2 = (((size_t)(b2 * NH + h)) * SEQ + s2) * DKV + d;
                uint32_t hi, lo;
                split2(v0, v1, hi, lo);
                *(uint32_t*)&Chi[o1] = hi; *(uint32_t*)&Clo[o1] = lo;
                split2(v2, v3, hi, lo);
                *(uint32_t*)&Chi[o2] = hi; *(uint32_t*)&Clo[o2] = lo;
            }
        }
    }
}

// ---------------- scores = Q K^T, tensor-core hi/lo ----------------
#define QKPAD 72
#define QK_SMEM (4 * 128 * QKPAD * 2)

__global__ __launch_bounds__(256) void qk_mma_kernel(float* __restrict__ wts) {
    extern __shared__ char qsm[];
    __nv_bfloat16 (*sQh)[QKPAD] = reinterpret_cast<__nv_bfloat16(*)[QKPAD]>(qsm);
    __nv_bfloat16 (*sQl)[QKPAD] = sQh + 128;
    __nv_bfloat16 (*sKh)[QKPAD] = sQl + 128;
    __nv_bfloat16 (*sKl)[QKPAD] = sKh + 128;

    const int tid = threadIdx.x, wid = tid >> 5, lane = tid & 31;
    const int q0 = blockIdx.x * 128;
    const int bh = blockIdx.y;
    const size_t base = (size_t)bh * SEQ * DKV;
    float* sp = wts + (size_t)bh * SEQ * SEQ;

    const int mw = (wid & 3) * 32;
    const int nw = (wid >> 2) * 64;
    const int arow = lane & 15;
    const int acol0 = (lane >> 4) << 3;
    const int brow = lane & 7;
    const int bcol0 = ((lane >> 3) & 1) << 3;

    // load Q tile (persistent)
#pragma unroll
    for (int it = 0; it < 4; it++) {
        int i = tid + it * 256;
        int r = i >> 3, seg = i & 7;
        size_t o = base + (size_t)(q0 + r) * DKV + seg * 8;
        *(uint4*)&sQh[r][seg * 8] = *(const uint4*)(g_qhi + o);
        *(uint4*)&sQl[r][seg * 8] = *(const uint4*)(g_qlo + o);
    }

    for (int kt = 0; kt < 16; kt++) {
        __syncthreads();
#pragma unroll
        for (int it = 0; it < 4; it++) {
            int i = tid + it * 256;
            int r = i >> 3, seg = i & 7;
            size_t o = base + (size_t)(kt * 128 + r) * DKV + seg * 8;
            *(uint4*)&sKh[r][seg * 8] = *(const uint4*)(g_khi + o);
            *(uint4*)&sKl[r][seg * 8] = *(const uint4*)(g_klo + o);
        }
        __syncthreads();

        float acc[2][8][4];
#pragma unroll
        for (int mt = 0; mt < 2; mt++)
#pragma unroll
            for (int nt = 0; nt < 8; nt++)
#pragma unroll
                for (int i = 0; i < 4; i++) acc[mt][nt][i] = 0.f;

#pragma unroll
        for (int kk = 0; kk < 64; kk += 16) {
            uint32_t aHi[2][4], aLo[2][4];
#pragma unroll
            for (int mt = 0; mt < 2; mt++) {
                uint32_t ah = smem_u32(&sQh[mw + mt * 16 + arow][kk + acol0]);
                LDSM_X4(aHi[mt][0], aHi[mt][1], aHi[mt][2], aHi[mt][3], ah);
                uint32_t al = smem_u32(&sQl[mw + mt * 16 + arow][kk + acol0]);
                LDSM_X4(aLo[mt][0], aLo[mt][1], aLo[mt][2], aLo[mt][3], al);
            }
#pragma unroll
            for (int g = 0; g < 2; g++) {
                uint32_t bHi[4][2], bLo[4][2];
#pragma unroll
                for (int j = 0; j < 4; j++) {
                    int nt = g * 4 + j;
                    uint32_t bh2 = smem_u32(&sKh[nw + nt * 8 + brow][kk + bcol0]);
                    LDSM_X2(bHi[j][0], bHi[j][1], bh2);
                    uint32_t bl2 = smem_u32(&sKl[nw + nt * 8 + brow][kk + bcol0]);
                    LDSM_X2(bLo[j][0], bLo[j][1], bl2);
                }
#pragma unroll
                for (int mt = 0; mt < 2; mt++)
#pragma unroll
                    for (int j = 0; j < 4; j++) {
                        int nt = g * 4 + j;
                        mma16816(acc[mt][nt], aHi[mt], bHi[j]);
                        mma16816(acc[mt][nt], aHi[mt], bLo[j]);
                        mma16816(acc[mt][nt], aLo[mt], bHi[j]);
                    }
            }
        }

#pragma unroll
        for (int mt = 0; mt < 2; mt++) {
            int r = q0 + mw + mt * 16 + (lane >> 2);
            float* row0 = sp + (size_t)r * SEQ + kt * 128;
            float* row1 = row0 + 8 * SEQ;
#pragma unroll
            for (int nt = 0; nt < 8; nt++) {
                int c = nw + nt * 8 + (lane & 3) * 2;
                *(float2*)&row0[c] = make_float2(acc[mt][nt][0], acc[mt][nt][1]);
                *(float2*)&row1[c] = make_float2(acc[mt][nt][2], acc[mt][nt][3]);
            }
        }
    }
}

// ---------------- softmax in-place; emits pos_bias output from b==0 blocks ----------------
__global__ __launch_bounds__(256) void softmax_kernel(float* __restrict__ wts,
                                                      float* __restrict__ pb)
{
    const int row = blockIdx.x;
    const int q = row & (SEQ - 1);
    const int bh = row >> 11;
    const int h = bh & 15, b = bh >> 4;
    float* wp = wts + (size_t)row * SEQ;
    const float* bias_h = g_bias + (h << 12) + (SEQ - 1) - q;
    const float* mrow = g_maskf + b * SEQ;
    float* pbrow = pb + ((size_t)(h * SEQ + q)) * SEQ;
    const int tid = threadIdx.x;

    __shared__ float sm[8], ss[8];
    float v[8];
    float mx = -INFINITY;
#pragma unroll
    for (int i = 0; i < 8; i++) {
        int kk = tid + (i << 8);
        float bv = bias_h[kk];
        if (b == 0) pbrow[kk] = bv;
        float val = wp[kk] + bv + mrow[kk];
        v[i] = val;
        mx = fmaxf(mx, val);
    }
    for (int o = 16; o; o >>= 1) mx = fmaxf(mx, __shfl_xor_sync(0xffffffffu, mx, o));
    if ((tid & 31) == 0) sm[tid >> 5] = mx;
    __syncthreads();
    mx = sm[0];
#pragma unroll
    for (int w = 1; w < 8; w++) mx = fmaxf(mx, sm[w]);

    float sum = 0.f;
#pragma unroll
    for (int i = 0; i < 8; i++) { v[i] = expf(v[i] - mx); sum += v[i]; }
    for (int o = 16; o; o >>= 1) sum += __shfl_xor_sync(0xffffffffu, sum, o);
    if ((tid & 31) == 0) ss[tid >> 5] = sum;
    __syncthreads();
    sum = 0.f;
#pragma unroll
    for (int w = 0; w < 8; w++) sum += ss[w];
    float inv = 1.0f / sum;
#pragma unroll
    for (int i = 0; i < 8; i++) wp[tid + (i << 8)] = v[i] * inv;
}

// ---------------- ctx = weights @ V, tensor-core hi/lo ----------------
__global__ __launch_bounds__(256) void wv_mma_kernel(const float* __restrict__ wts) {
    __shared__ __nv_bfloat16 sWh[128][APAD], sWl[128][APAD];
    __shared__ __nv_bfloat16 sVh[64][APAD], sVl[64][APAD];

    const int tid = threadIdx.x, wid = tid >> 5, lane = tid & 31;
    const int m0 = blockIdx.x * 128;
    const int bh = blockIdx.y;
    const int b = bh >> 4, h = bh & 15;
    const float* wp = wts + (size_t)bh * SEQ * SEQ;
    const __nv_bfloat16* vh = g_vthi + (size_t)bh * DKV * SEQ;
    const __nv_bfloat16* vl = g_vtlo + (size_t)bh * DKV * SEQ;

    const int mw = (wid & 3) * 32;
    const int nw = (wid >> 2) * 32;
    const int arow = lane & 15;
    const int acol0 = (lane >> 4) << 3;
    const int brow = lane & 7;
    const int bcol0 = ((lane >> 3) & 1) << 3;

    float acc[2][4][4];
#pragma unroll
    for (int mt = 0; mt < 2; mt++)
#pragma unroll
        for (int nt = 0; nt < 4; nt++)
#pragma unroll
            for (int i = 0; i < 4; i++) acc[mt][nt][i] = 0.f;

    for (int k0 = 0; k0 < SEQ; k0 += 32) {
        __syncthreads();
        // W tile: 128 x 32 f32, convert to hi/lo
#pragma unroll
        for (int it = 0; it < 4; it++) {
            int i = tid + it * 256;
            int r = i >> 3, seg = i & 7;
            float4 v = *(const float4*)&wp[(size_t)(m0 + r) * SEQ + k0 + seg * 4];
            uint2 H, L;
            split2(v.x, v.y, H.x, L.x);
            split2(v.z, v.w, H.y, L.y);
            *(uint2*)&sWh[r][seg * 4] = H;
            *(uint2*)&sWl[r][seg * 4] = L;
        }
        // V tile: 64(d) x 32(s) bf16 hi/lo
        {
            int r = tid >> 2, seg = tid & 3;
            *(uint4*)&sVh[r][seg * 8] = *(const uint4*)(vh + (size_t)r * SEQ + k0 + seg * 8);
            *(uint4*)&sVl[r][seg * 8] = *(const uint4*)(vl + (size_t)r * SEQ + k0 + seg * 8);
        }
        __syncthreads();

#pragma unroll
        for (int kk = 0; kk < 32; kk += 16) {
            uint32_t aHi[2][4], aLo[2][4], bHi[4][2], bLo[4][2];
#pragma unroll
            for (int mt = 0; mt < 2; mt++) {
                uint32_t ah = smem_u32(&sWh[mw + mt * 16 + arow][kk + acol0]);
                LDSM_X4(aHi[mt][0], aHi[mt][1], aHi[mt][2], aHi[mt][3], ah);
                uint32_t al = smem_u32(&sWl[mw + mt * 16 + arow][kk + acol0]);
                LDSM_X4(aLo[mt][0], aLo[mt][1], aLo[mt][2], aLo[mt][3], al);
            }
#pragma unroll
            for (int nt = 0; nt < 4; nt++) {
                uint32_t bh2 = smem_u32(&sVh[nw + nt * 8 + brow][kk + bcol0]);
                LDSM_X2(bHi[nt][0], bHi[nt][1], bh2);
                uint32_t bl2 = smem_u32(&sVl[nw + nt * 8 + brow][kk + bcol0]);
                LDSM_X2(bLo[nt][0], bLo[nt][1], bl2);
            }
#pragma unroll
            for (int mt = 0; mt < 2; mt++)
#pragma unroll
                for (int nt = 0; nt < 4; nt++) {
                    mma16816(acc[mt][nt], aHi[mt], bHi[nt]);
                    mma16816(acc[mt][nt], aHi[mt], bLo[nt]);
                    mma16816(acc[mt][nt], aLo[mt], bHi[nt]);
                }
        }
    }

    // epilogue: ctx (b, s, h*64+d) bf16 hi/lo
#pragma unroll
    for (int mt = 0; mt < 2; mt++) {
        int s = m0 + mw + mt * 16 + (lane >> 2);
#pragma unroll
        for (int nt = 0; nt < 4; nt++) {
            int d = nw + nt * 8 + (lane & 3) * 2;
            size_t o1 = ((size_t)(b * SEQ + s)) * INNER + h * DKV + d;
            size_t o2 = ((size_t)(b * SEQ + s + 8)) * INNER + h * DKV + d;
            uint32_t hi, lo;
            split2(acc[mt][nt][0], acc[mt][nt][1], hi, lo);
            *(uint32_t*)&g_chi[o1] = hi; *(uint32_t*)&g_clo[o1] = lo;
            split2(acc[mt][nt][2], acc[mt][nt][3], hi, lo);
            *(uint32_t*)&g_chi[o2] = hi; *(uint32_t*)&g_clo[o2] = lo;
        }
    }
}

// ---------------- launch ----------------
extern "C" void kernel_launch(void* const* d_in, const int* in_sizes, int n_in,
                              void* d_out, int out_size) {
    const float* x  = (const float*)d_in[0];
    const float* Wq = (const float*)d_in[1];
    const float* bq = (const float*)d_in[2];
    const float* Wk = (const float*)d_in[3];
    const float* bk = (const float*)d_in[4];
    const float* Wv = (const float*)d_in[5];
    const float* bv = (const float*)d_in[6];
    const float* Wo = (const float*)d_in[7];
    const float* bo = (const float*)d_in[8];
    const float* rel_table = (const float*)d_in[9];
    const unsigned char* mask = (const unsigned char*)d_in[10];

    float* out = (float*)d_out;
    float* wts = out + (size_t)BSZ * SEQ * DMODEL;
    float* pb  = wts + (size_t)BSZ * NH * SEQ * SEQ;

    __nv_bfloat16 *pxhi, *pxlo, *pwhi, *pwlo, *pchi, *pclo;
    __nv_bfloat16 *pqhi, *pqlo, *pkhi, *pklo, *pvhi, *pvlo;
    cudaGetSymbolAddress((void**)&pxhi, g_xhi);
    cudaGetSymbolAddress((void**)&pxlo, g_xlo);
    cudaGetSymbolAddress((void**)&pwhi, g_whi);
    cudaGetSymbolAddress((void**)&pwlo, g_wlo);
    cudaGetSymbolAddress((void**)&pchi, g_chi);
    cudaGetSymbolAddress((void**)&pclo, g_clo);
    cudaGetSymbolAddress((void**)&pqhi, g_qhi);
    cudaGetSymbolAddress((void**)&pqlo, g_qlo);
    cudaGetSymbolAddress((void**)&pkhi, g_khi);
    cudaGetSymbolAddress((void**)&pklo, g_klo);
    cudaGetSymbolAddress((void**)&pvhi, g_vhi);
    cudaGetSymbolAddress((void**)&pvlo, g_vlo);

    cudaFuncSetAttribute(qk_mma_kernel,
                         cudaFuncAttributeMaxDynamicSharedMemorySize, QK_SMEM);

    const size_t WSTRIDE = (size_t)DMODEL * INNER;

    maskprep_kernel<<<1, 1024>>>(mask);
    biasfill_kernel<<<256, 256>>>(rel_table);

    cvt_split_kernel<<<(MTOT * DMODEL) / 1024, 256>>>(x, pxhi, pxlo);
    dim3 tg(32, 32);
    transpose_split_kernel<<<tg, 256>>>(Wq, pwhi + 0 * WSTRIDE, pwlo + 0 * WSTRIDE);
    transpose_split_kernel<<<tg, 256>>>(Wk, pwhi + 1 * WSTRIDE, pwlo + 1 * WSTRIDE);
    transpose_split_kernel<<<tg, 256>>>(Wv, pwhi + 2 * WSTRIDE, pwlo + 2 * WSTRIDE);
    transpose_split_kernel<<<tg, 256>>>(Wo, pwhi + 3 * WSTRIDE, pwlo + 3 * WSTRIDE);

    dim3 gg(INNER / 64, MTOT / 128);   // (16, 32)
    mma_gemm_kernel<<<gg, 256>>>(pxhi, pxlo, pwhi + 0 * WSTRIDE, pwlo + 0 * WSTRIDE, bq,
                                 nullptr, pqhi, pqlo, 1);
    mma_gemm_kernel<<<gg, 256>>>(pxhi, pxlo, pwhi + 1 * WSTRIDE, pwlo + 1 * WSTRIDE, bk,
                                 nullptr, pkhi, pklo, 1);
    mma_gemm_kernel<<<gg, 256>>>(pxhi, pxlo, pwhi + 2 * WSTRIDE, pwlo + 2 * WSTRIDE, bv,
                                 nullptr, pvhi, pvlo, 1);

    vtrans_kernel<<<dim3(SEQ / 32, DKV / 32, BSZ * NH), 256>>>();

    qk_mma_kernel<<<dim3(SEQ / 128, BSZ * NH), 256, QK_SMEM>>>(wts);

    softmax_kernel<<<BSZ * NH * SEQ, 256>>>(wts, pb);

    wv_mma_kernel<<<dim3(SEQ / 128, BSZ * NH), 256>>>(wts);

    mma_gemm_kernel<<<gg, 256>>>(pchi, pclo, pwhi + 3 * WSTRIDE, pwlo + 3 * WSTRIDE, bo,
                                 out, nullptr, nullptr, 0);
}

// round 10
// speedup vs baseline: 2.1800x; 1.1712x over previous
#include <cuda_runtime.h>
#include <cuda_bf16.h>
#include <math.h>
#include <stdint.h>

#define BSZ 2
#define SEQ 2048
#define NH 16
#define DKV 64
#define DMODEL 1024
#define INNER 1024
#define MTOT (BSZ * SEQ)   // 4096

// ---------------- scratch (static device memory; no allocations) ----------------
__device__ float g_bias[NH * 4096];
__device__ float g_maskf[BSZ * SEQ];
__device__ __nv_bfloat16 g_xhi[MTOT * DMODEL];
__device__ __nv_bfloat16 g_xlo[MTOT * DMODEL];
__device__ __nv_bfloat16 g_whi[4u * DMODEL * INNER];   // [n][k]; 0=Wq 1=Wk 2=Wv 3=Wo
__device__ __nv_bfloat16 g_wlo[4u * DMODEL * INNER];
__device__ __nv_bfloat16 g_qhi[BSZ * NH * SEQ * DKV];  // (b,h,s,d)
__device__ __nv_bfloat16 g_qlo[BSZ * NH * SEQ * DKV];
__device__ __nv_bfloat16 g_khi[BSZ * NH * SEQ * DKV];
__device__ __nv_bfloat16 g_klo[BSZ * NH * SEQ * DKV];
__device__ __nv_bfloat16 g_vhi[BSZ * NH * SEQ * DKV];
__device__ __nv_bfloat16 g_vlo[BSZ * NH * SEQ * DKV];
__device__ __nv_bfloat16 g_vthi[BSZ * NH * DKV * SEQ]; // (b,h,d,s)
__device__ __nv_bfloat16 g_vtlo[BSZ * NH * DKV * SEQ];
__device__ __nv_bfloat16 g_chi[MTOT * INNER];          // (b,s,inner)
__device__ __nv_bfloat16 g_clo[MTOT * INNER];

// ---------------- PTX helpers ----------------
__device__ __forceinline__ uint32_t smem_u32(const void* p) {
    uint32_t a;
    asm("{ .reg .u64 t; cvta.to.shared.u64 t, %1; cvt.u32.u64 %0, t; }" : "=r"(a) : "l"(p));
    return a;
}
#define LDSM_X4(r0, r1, r2, r3, addr) \
    asm volatile("ldmatrix.sync.aligned.m8n8.x4.shared.b16 {%0,%1,%2,%3}, [%4];" \
                 : "=r"(r0), "=r"(r1), "=r"(r2), "=r"(r3) : "r"(addr))
#define LDSM_X2(r0, r1, addr) \
    asm volatile("ldmatrix.sync.aligned.m8n8.x2.shared.b16 {%0,%1}, [%2];" \
                 : "=r"(r0), "=r"(r1) : "r"(addr))
#define CP_ASYNC16(dst, src) \
    asm volatile("cp.async.cg.shared.global [%0], [%1], 16;" :: "r"(dst), "l"(src))
#define CP_COMMIT() asm volatile("cp.async.commit_group;" ::: "memory")
#define CP_WAIT0()  asm volatile("cp.async.wait_group 0;" ::: "memory")
#define CP_WAIT1()  asm volatile("cp.async.wait_group 1;" ::: "memory")

__device__ __forceinline__ void mma16816(float* c, const uint32_t* a, const uint32_t* b) {
    asm volatile("mma.sync.aligned.m16n8k16.row.col.f32.bf16.bf16.f32 "
                 "{%0,%1,%2,%3}, {%4,%5,%6,%7}, {%8,%9}, {%0,%1,%2,%3};"
                 : "+f"(c[0]), "+f"(c[1]), "+f"(c[2]), "+f"(c[3])
                 : "r"(a[0]), "r"(a[1]), "r"(a[2]), "r"(a[3]), "r"(b[0]), "r"(b[1]));
}

__device__ __forceinline__ void split2(float v0, float v1, uint32_t& hi, uint32_t& lo) {
    __nv_bfloat16 h0 = __float2bfloat16(v0), h1 = __float2bfloat16(v1);
    __nv_bfloat16 l0 = __float2bfloat16(v0 - __bfloat162float(h0));
    __nv_bfloat16 l1 = __float2bfloat16(v1 - __bfloat162float(h1));
    hi = (uint32_t)__bfloat16_as_ushort(h0) | ((uint32_t)__bfloat16_as_ushort(h1) << 16);
    lo = (uint32_t)__bfloat16_as_ushort(l0) | ((uint32_t)__bfloat16_as_ushort(l1) << 16);
}

// ---------------- mask preprocessing (bool stored as int32) ----------------
__global__ void maskprep_kernel(const unsigned char* __restrict__ mraw) {
    __shared__ int s_nonzero;
    const int tid = threadIdx.x;
    if (tid == 0) s_nonzero = 0;
    __syncthreads();
    int cnt = 0;
    for (int i = tid; i < BSZ * SEQ; i += 1024)
        if ((i & 3) && mraw[i]) cnt++;
    if (cnt) atomicAdd(&s_nonzero, cnt);
    __syncthreads();
    const bool is_u8 = (s_nonzero > 0);
    const int* mi = (const int*)mraw;
    for (int i = tid; i < BSZ * SEQ; i += 1024) {
        int flag = is_u8 ? (int)mraw[i] : mi[i];
        g_maskf[i] = flag ? -INFINITY : 0.0f;
    }
}

// ---------------- T5 relative-position bucket ----------------
__device__ __forceinline__ int rel_bucket(int delta) {
    int ret = (delta > 0) ? 32 : 0;
    int n = (delta < 0) ? -delta : delta;
    if (n < 16) return ret + n;
    float t = logf((float)n / 16.0f);
    t = t / 1.1394342831883648f;
    t = t * 16.0f;
    int large = 16 + (int)t;
    if (large > 31) large = 31;
    return ret + large;
}

__global__ void biasfill_kernel(const float* __restrict__ rel_table) {
    int idx = blockIdx.x * 256 + threadIdx.x;
    int h = idx >> 12;
    int dd = idx & 4095;
    int delta = dd - (SEQ - 1);
    if (dd >= 2 * SEQ - 1) delta = 0;
    g_bias[idx] = rel_table[rel_bucket(delta) * NH + h];
}

// ---------------- f32 -> bf16 hi/lo split ----------------
__global__ void cvt_split_kernel(const float* __restrict__ src,
                                 __nv_bfloat16* __restrict__ dhi,
                                 __nv_bfloat16* __restrict__ dlo) {
    size_t i = ((size_t)blockIdx.x * 256 + threadIdx.x) * 4;
    float4 v = *(const float4*)(src + i);
    uint2 H, L;
    split2(v.x, v.y, H.x, L.x);
    split2(v.z, v.w, H.y, L.y);
    *(uint2*)(dhi + i) = H;
    *(uint2*)(dlo + i) = L;
}

// ---------------- W [K][N] f32 -> Wt [N][K] bf16 hi/lo ----------------
__global__ void transpose_split_kernel(const float* __restrict__ src,
                                       __nv_bfloat16* __restrict__ dhi,
                                       __nv_bfloat16* __restrict__ dlo) {
    __shared__ float t[32][33];
    int tx = threadIdx.x & 31, ty = threadIdx.x >> 5;
    int n0 = blockIdx.x * 32, k0 = blockIdx.y * 32;
#pragma unroll
    for (int j = 0; j < 32; j += 8)
        t[ty + j][tx] = src[(size_t)(k0 + ty + j) * INNER + n0 + tx];
    __syncthreads();
#pragma unroll
    for (int j = 0; j < 32; j += 8) {
        float v = t[tx][ty + j];
        int n = n0 + ty + j, k = k0 + tx;
        __nv_bfloat16 h = __float2bfloat16(v);
        dhi[(size_t)n * DMODEL + k] = h;
        dlo[(size_t)n * DMODEL + k] = __float2bfloat16(v - __bfloat162float(h));
    }
}

// ---------------- V (b,h,s,d) -> Vt (b,h,d,s), bf16 hi+lo ----------------
__global__ void vtrans_kernel() {
    __shared__ unsigned short th[32][33], tl[32][33];
    const int tx = threadIdx.x & 31, ty = threadIdx.x >> 5;
    const int s0 = blockIdx.x * 32, d0 = blockIdx.y * 32, bh = blockIdx.z;
    const size_t base = (size_t)bh * SEQ * DKV;
#pragma unroll
    for (int j = 0; j < 32; j += 8) {
        size_t o = base + (size_t)(s0 + ty + j) * DKV + d0 + tx;
        th[ty + j][tx] = __bfloat16_as_ushort(g_vhi[o]);
        tl[ty + j][tx] = __bfloat16_as_ushort(g_vlo[o]);
    }
    __syncthreads();
#pragma unroll
    for (int j = 0; j < 32; j += 8) {
        size_t o = base + (size_t)(d0 + ty + j) * SEQ + s0 + tx;
        g_vthi[o] = __ushort_as_bfloat16(th[tx][ty + j]);
        g_vtlo[o] = __ushort_as_bfloat16(tl[tx][ty + j]);
    }
}

// ---------------- pipelined mma.sync GEMM: [4096 x 1024] = A * B^T + bias ----------------
#define APAD 40
#define GA_ELE (2 * 128 * APAD)   // A elems per stage (both halves)
#define GB_ELE (2 * 64 * APAD)
#define GEMM_SMEM ((2 * (GA_ELE + GB_ELE)) * 2)   // bytes

__global__ __launch_bounds__(256) void mma_gemm_kernel(
    const __nv_bfloat16* __restrict__ Ahi, const __nv_bfloat16* __restrict__ Alo,
    const __nv_bfloat16* __restrict__ Bhi, const __nv_bfloat16* __restrict__ Blo,
    const float* __restrict__ bias, float* __restrict__ C,
    __nv_bfloat16* __restrict__ Chi, __nv_bfloat16* __restrict__ Clo, int mode)
{
    extern __shared__ char gsm_raw[];
    __nv_bfloat16* sA = (__nv_bfloat16*)gsm_raw;            // [st][half][128][APAD]
    __nv_bfloat16* sB = sA + 2 * GA_ELE;                    // [st][half][64][APAD]

    const int tid = threadIdx.x;
    const int wid = tid >> 5, lane = tid & 31;
    const int m0 = blockIdx.y * 128;
    const int n0b = blockIdx.x * 64;
    const int mw = (wid & 3) * 32;
    const int nw = (wid >> 2) * 32;

    float acc[2][4][4];
#pragma unroll
    for (int mt = 0; mt < 2; mt++)
#pragma unroll
        for (int nt = 0; nt < 4; nt++)
#pragma unroll
            for (int i = 0; i < 4; i++) acc[mt][nt][i] = 0.f;

    const int arow = lane & 15;
    const int acol0 = (lane >> 4) << 3;
    const int brow = lane & 7;
    const int bcol0 = ((lane >> 3) & 1) << 3;

    auto load_stage = [&](int st, int k0) {
#pragma unroll
        for (int h = 0; h < 2; h++) {
            const __nv_bfloat16* as = h ? Alo : Ahi;
#pragma unroll
            for (int it = 0; it < 2; it++) {
                int idx = tid + it * 256;
                int r = idx >> 2, seg = idx & 3;
                uint32_t dst = smem_u32(sA + ((st * 2 + h) * 128 + r) * APAD + seg * 8);
                CP_ASYNC16(dst, as + (size_t)(m0 + r) * 1024 + k0 + seg * 8);
            }
            const __nv_bfloat16* bs = h ? Blo : Bhi;
            {
                int r = tid >> 2, seg = tid & 3;
                uint32_t dst = smem_u32(sB + ((st * 2 + h) * 64 + r) * APAD + seg * 8);
                CP_ASYNC16(dst, bs + (size_t)(n0b + r) * 1024 + k0 + seg * 8);
            }
        }
    };

    load_stage(0, 0);  CP_COMMIT();
    load_stage(1, 32); CP_COMMIT();

    const int NC = 1024 / 32;
    for (int c = 0; c < NC; c++) {
        if (c == NC - 1) CP_WAIT0(); else CP_WAIT1();
        __syncthreads();
        const int st = c & 1;
        __nv_bfloat16* aH = sA + (st * 2 + 0) * 128 * APAD;
        __nv_bfloat16* aL = sA + (st * 2 + 1) * 128 * APAD;
        __nv_bfloat16* bH = sB + (st * 2 + 0) * 64 * APAD;
        __nv_bfloat16* bL = sB + (st * 2 + 1) * 64 * APAD;
#pragma unroll
        for (int kk = 0; kk < 32; kk += 16) {
            uint32_t aHi[2][4], aLo[2][4], bHi[4][2], bLo[4][2];
#pragma unroll
            for (int mt = 0; mt < 2; mt++) {
                uint32_t ah = smem_u32(aH + (mw + mt * 16 + arow) * APAD + kk + acol0);
                LDSM_X4(aHi[mt][0], aHi[mt][1], aHi[mt][2], aHi[mt][3], ah);
                uint32_t al = smem_u32(aL + (mw + mt * 16 + arow) * APAD + kk + acol0);
                LDSM_X4(aLo[mt][0], aLo[mt][1], aLo[mt][2], aLo[mt][3], al);
            }
#pragma unroll
            for (int nt = 0; nt < 4; nt++) {
                uint32_t bh = smem_u32(bH + (nw + nt * 8 + brow) * APAD + kk + bcol0);
                LDSM_X2(bHi[nt][0], bHi[nt][1], bh);
                uint32_t bl = smem_u32(bL + (nw + nt * 8 + brow) * APAD + kk + bcol0);
                LDSM_X2(bLo[nt][0], bLo[nt][1], bl);
            }
#pragma unroll
            for (int mt = 0; mt < 2; mt++)
#pragma unroll
                for (int nt = 0; nt < 4; nt++) {
                    mma16816(acc[mt][nt], aHi[mt], bHi[nt]);
                    mma16816(acc[mt][nt], aHi[mt], bLo[nt]);
                    mma16816(acc[mt][nt], aLo[mt], bHi[nt]);
                }
        }
        __syncthreads();
        if (c + 2 < NC) { load_stage(st, (c + 2) * 32); CP_COMMIT(); }
    }

#pragma unroll
    for (int mt = 0; mt < 2; mt++) {
        int r = m0 + mw + mt * 16 + (lane >> 2);
#pragma unroll
        for (int nt = 0; nt < 4; nt++) {
            int n = n0b + nw + nt * 8 + (lane & 3) * 2;
            float v0 = acc[mt][nt][0] + bias[n], v1 = acc[mt][nt][1] + bias[n + 1];
            float v2 = acc[mt][nt][2] + bias[n], v3 = acc[mt][nt][3] + bias[n + 1];
            if (mode == 0) {
                *(float2*)&C[(size_t)r * 1024 + n] = make_float2(v0, v1);
                *(float2*)&C[(size_t)(r + 8) * 1024 + n] = make_float2(v2, v3);
            } else {
                int h = n >> 6, d = n & 63;
                int b = r >> 11, s = r & (SEQ - 1);
                size_t o1 = (((size_t)(b * NH + h)) * SEQ + s) * DKV + d;
                int b2 = (r + 8) >> 11, s2 = (r + 8) & (SEQ - 1);
                size_t o2 = (((size_t)(b2 * NH + h)) * SEQ + s2) * DKV + d;
                uint32_t hi, lo;
                split2(v0, v1, hi, lo);
                *(uint32_t*)&Chi[o1] = hi; *(uint32_t*)&Clo[o1] = lo;
                split2(v2, v3, hi, lo);
                *(uint32_t*)&Chi[o2] = hi; *(uint32_t*)&Clo[o2] = lo;
            }
        }
    }
}

// ---------------- scores = Q K^T, pipelined hi/lo ----------------
#define QKPAD 72
#define QK_TILE (2 * 128 * QKPAD)                 // elems per (half-pair) tile
#define QK_SMEM ((QK_TILE * 3) * 2)               // bytes: Q + 2 K stages

__global__ __launch_bounds__(256) void qk_mma_kernel(float* __restrict__ wts) {
    extern __shared__ char qsm_raw[];
    __nv_bfloat16* sQ = (__nv_bfloat16*)qsm_raw;  // [half][128][QKPAD]
    __nv_bfloat16* sK = sQ + QK_TILE;             // [st][half][128][QKPAD]

    const int tid = threadIdx.x, wid = tid >> 5, lane = tid & 31;
    const int q0 = blockIdx.x * 128;
    const int bh = blockIdx.y;
    const size_t base = (size_t)bh * SEQ * DKV;
    float* sp = wts + (size_t)bh * SEQ * SEQ;

    const int mw = (wid & 3) * 32;
    const int nw = (wid >> 2) * 64;
    const int arow = lane & 15;
    const int acol0 = (lane >> 4) << 3;
    const int brow = lane & 7;
    const int bcol0 = ((lane >> 3) & 1) << 3;

    // Q tile (persistent, synchronous)
#pragma unroll
    for (int it = 0; it < 4; it++) {
        int i = tid + it * 256;
        int r = i >> 3, seg = i & 7;
        size_t o = base + (size_t)(q0 + r) * DKV + seg * 8;
        *(uint4*)(sQ + r * QKPAD + seg * 8) = *(const uint4*)(g_qhi + o);
        *(uint4*)(sQ + (128 + r) * QKPAD + seg * 8) = *(const uint4*)(g_qlo + o);
    }

    auto load_k = [&](int st, int kt) {
#pragma unroll
        for (int h = 0; h < 2; h++) {
            const __nv_bfloat16* ks = h ? g_klo : g_khi;
#pragma unroll
            for (int it = 0; it < 4; it++) {
                int i = tid + it * 256;
                int r = i >> 3, seg = i & 7;
                uint32_t dst = smem_u32(sK + ((st * 2 + h) * 128 + r) * QKPAD + seg * 8);
                CP_ASYNC16(dst, ks + base + (size_t)(kt * 128 + r) * DKV + seg * 8);
            }
        }
    };

    load_k(0, 0); CP_COMMIT();
    load_k(1, 1); CP_COMMIT();

    for (int kt = 0; kt < 16; kt++) {
        if (kt == 15) CP_WAIT0(); else CP_WAIT1();
        __syncthreads();
        const int st = kt & 1;
        __nv_bfloat16* kH = sK + (st * 2 + 0) * 128 * QKPAD;
        __nv_bfloat16* kL = sK + (st * 2 + 1) * 128 * QKPAD;

        float acc[2][8][4];
#pragma unroll
        for (int mt = 0; mt < 2; mt++)
#pragma unroll
            for (int nt = 0; nt < 8; nt++)
#pragma unroll
                for (int i = 0; i < 4; i++) acc[mt][nt][i] = 0.f;

#pragma unroll
        for (int kk = 0; kk < 64; kk += 16) {
            uint32_t aHi[2][4], aLo[2][4];
#pragma unroll
            for (int mt = 0; mt < 2; mt++) {
                uint32_t ah = smem_u32(sQ + (mw + mt * 16 + arow) * QKPAD + kk + acol0);
                LDSM_X4(aHi[mt][0], aHi[mt][1], aHi[mt][2], aHi[mt][3], ah);
                uint32_t al = smem_u32(sQ + (128 + mw + mt * 16 + arow) * QKPAD + kk + acol0);
                LDSM_X4(aLo[mt][0], aLo[mt][1], aLo[mt][2], aLo[mt][3], al);
            }
#pragma unroll
            for (int g = 0; g < 2; g++) {
                uint32_t bHi[4][2], bLo[4][2];
#pragma unroll
                for (int j = 0; j < 4; j++) {
                    int nt = g * 4 + j;
                    uint32_t bh2 = smem_u32(kH + (nw + nt * 8 + brow) * QKPAD + kk + bcol0);
                    LDSM_X2(bHi[j][0], bHi[j][1], bh2);
                    uint32_t bl2 = smem_u32(kL + (nw + nt * 8 + brow) * QKPAD + kk + bcol0);
                    LDSM_X2(bLo[j][0], bLo[j][1], bl2);
                }
#pragma unroll
                for (int mt = 0; mt < 2; mt++)
#pragma unroll
                    for (int j = 0; j < 4; j++) {
                        int nt = g * 4 + j;
                        mma16816(acc[mt][nt], aHi[mt], bHi[j]);
                        mma16816(acc[mt][nt], aHi[mt], bLo[j]);
                        mma16816(acc[mt][nt], aLo[mt], bHi[j]);
                    }
            }
        }

#pragma unroll
        for (int mt = 0; mt < 2; mt++) {
            int r = q0 + mw + mt * 16 + (lane >> 2);
            float* row0 = sp + (size_t)r * SEQ + kt * 128;
            float* row1 = row0 + 8 * SEQ;
#pragma unroll
            for (int nt = 0; nt < 8; nt++) {
                int c = nw + nt * 8 + (lane & 3) * 2;
                *(float2*)&row0[c] = make_float2(acc[mt][nt][0], acc[mt][nt][1]);
                *(float2*)&row1[c] = make_float2(acc[mt][nt][2], acc[mt][nt][3]);
            }
        }
        __syncthreads();
        if (kt + 2 < 16) { load_k(st, kt + 2); CP_COMMIT(); }
    }
}

// ---------------- softmax in-place (vectorized); emits pos_bias from b==0 ----------------
__global__ __launch_bounds__(256) void softmax_kernel(float* __restrict__ wts,
                                                      float* __restrict__ pb)
{
    const int row = blockIdx.x;
    const int q = row & (SEQ - 1);
    const int bh = row >> 11;
    const int h = bh & 15, b = bh >> 4;
    float* wp = wts + (size_t)row * SEQ;
    const float* bias_h = g_bias + (h << 12) + (SEQ - 1) - q;
    const float* mrow = g_maskf + b * SEQ;
    float* pbrow = pb + ((size_t)(h * SEQ + q)) * SEQ;
    const int tid = threadIdx.x;
    const int k0 = tid * 8;

    __shared__ float sm[8], ss[8];
    float v[8], bvv[8];
    float4 s0 = *(float4*)&wp[k0], s1 = *(float4*)&wp[k0 + 4];
    float4 mk0 = *(float4*)&mrow[k0], mk1 = *(float4*)&mrow[k0 + 4];
    float sv[8] = {s0.x, s0.y, s0.z, s0.w, s1.x, s1.y, s1.z, s1.w};
    float mv[8] = {mk0.x, mk0.y, mk0.z, mk0.w, mk1.x, mk1.y, mk1.z, mk1.w};
    float mx = -INFINITY;
#pragma unroll
    for (int i = 0; i < 8; i++) {
        bvv[i] = bias_h[k0 + i];
        float val = sv[i] + bvv[i] + mv[i];
        v[i] = val;
        mx = fmaxf(mx, val);
    }
    if (b == 0) {
        *(float4*)&pbrow[k0] = make_float4(bvv[0], bvv[1], bvv[2], bvv[3]);
        *(float4*)&pbrow[k0 + 4] = make_float4(bvv[4], bvv[5], bvv[6], bvv[7]);
    }
    for (int o = 16; o; o >>= 1) mx = fmaxf(mx, __shfl_xor_sync(0xffffffffu, mx, o));
    if ((tid & 31) == 0) sm[tid >> 5] = mx;
    __syncthreads();
    mx = sm[0];
#pragma unroll
    for (int w = 1; w < 8; w++) mx = fmaxf(mx, sm[w]);

    float sum = 0.f;
#pragma unroll
    for (int i = 0; i < 8; i++) { v[i] = __expf(v[i] - mx); sum += v[i]; }
    for (int o = 16; o; o >>= 1) sum += __shfl_xor_sync(0xffffffffu, sum, o);
    if ((tid & 31) == 0) ss[tid >> 5] = sum;
    __syncthreads();
    sum = 0.f;
#pragma unroll
    for (int w = 0; w < 8; w++) sum += ss[w];
    float inv = 1.0f / sum;
    *(float4*)&wp[k0] = make_float4(v[0] * inv, v[1] * inv, v[2] * inv, v[3] * inv);
    *(float4*)&wp[k0 + 4] = make_float4(v[4] * inv, v[5] * inv, v[6] * inv, v[7] * inv);
}

// ---------------- ctx = weights @ V, pipelined hi/lo ----------------
#define WV_W_ELE (2 * 128 * APAD)                 // bf16 elems
#define WV_V_ELE (2 * 64 * APAD)                  // per stage
#define WV_SMEM (WV_W_ELE * 2 + 2 * WV_V_ELE * 2 + 2 * 128 * 32 * 4)

__global__ __launch_bounds__(256) void wv_mma_kernel(const float* __restrict__ wts) {
    extern __shared__ char wsm_raw[];
    __nv_bfloat16* sW = (__nv_bfloat16*)wsm_raw;             // [half][128][APAD]
    __nv_bfloat16* sV = sW + WV_W_ELE;                        // [st][half][64][APAD]
    float* sWraw = (float*)(sV + 2 * WV_V_ELE);               // [st][128][32]

    const int tid = threadIdx.x, wid = tid >> 5, lane = tid & 31;
    const int m0 = blockIdx.x * 128;
    const int bh = blockIdx.y;
    const int b = bh >> 4, h = bh & 15;
    const float* wp = wts + (size_t)bh * SEQ * SEQ;
    const __nv_bfloat16* vh = g_vthi + (size_t)bh * DKV * SEQ;
    const __nv_bfloat16* vl = g_vtlo + (size_t)bh * DKV * SEQ;

    const int mw = (wid & 3) * 32;
    const int nw = (wid >> 2) * 32;
    const int arow = lane & 15;
    const int acol0 = (lane >> 4) << 3;
    const int brow = lane & 7;
    const int bcol0 = ((lane >> 3) & 1) << 3;

    float acc[2][4][4];
#pragma unroll
    for (int mt = 0; mt < 2; mt++)
#pragma unroll
        for (int nt = 0; nt < 4; nt++)
#pragma unroll
            for (int i = 0; i < 4; i++) acc[mt][nt][i] = 0.f;

    auto load_stage = [&](int st, int k0) {
#pragma unroll
        for (int hh = 0; hh < 2; hh++) {
            const __nv_bfloat16* vs = hh ? vl : vh;
            int r = tid >> 2, seg = tid & 3;
            uint32_t dst = smem_u32(sV + ((st * 2 + hh) * 64 + r) * APAD + seg * 8);
            CP_ASYNC16(dst, vs + (size_t)r * SEQ + k0 + seg * 8);
        }
#pragma unroll
        for (int it = 0; it < 4; it++) {
            int i = tid + it * 256;
            int r = i >> 3, seg = i & 7;
            uint32_t dst = smem_u32(sWraw + (st * 128 + r) * 32 + seg * 4);
            CP_ASYNC16(dst, wp + (size_t)(m0 + r) * SEQ + k0 + seg * 4);
        }
    };

    load_stage(0, 0);  CP_COMMIT();
    load_stage(1, 32); CP_COMMIT();

    const int NC = SEQ / 32;
    for (int c = 0; c < NC; c++) {
        if (c == NC - 1) CP_WAIT0(); else CP_WAIT1();
        __syncthreads();
        const int st = c & 1;
#pragma unroll
        for (int it = 0; it < 4; it++) {
            int i = tid + it * 256;
            int r = i >> 3, seg = i & 7;
            float4 v = *(float4*)(sWraw + (st * 128 + r) * 32 + seg * 4);
            uint2 H, L;
            split2(v.x, v.y, H.x, L.x);
            split2(v.z, v.w, H.y, L.y);
            *(uint2*)(sW + r * APAD + seg * 4) = H;
            *(uint2*)(sW + (128 + r) * APAD + seg * 4) = L;
        }
        __syncthreads();

        __nv_bfloat16* vH = sV + (st * 2 + 0) * 64 * APAD;
        __nv_bfloat16* vL = sV + (st * 2 + 1) * 64 * APAD;
#pragma unroll
        for (int kk = 0; kk < 32; kk += 16) {
            uint32_t aHi[2][4], aLo[2][4], bHi[4][2], bLo[4][2];
#pragma unroll
            for (int mt = 0; mt < 2; mt++) {
                uint32_t ah = smem_u32(sW + (mw + mt * 16 + arow) * APAD + kk + acol0);
                LDSM_X4(aHi[mt][0], aHi[mt][1], aHi[mt][2], aHi[mt][3], ah);
                uint32_t al = smem_u32(sW + (128 + mw + mt * 16 + arow) * APAD + kk + acol0);
                LDSM_X4(aLo[mt][0], aLo[mt][1], aLo[mt][2], aLo[mt][3], al);
            }
#pragma unroll
            for (int nt = 0; nt < 4; nt++) {
                uint32_t bh2 = smem_u32(vH + (nw + nt * 8 + brow) * APAD + kk + bcol0);
                LDSM_X2(bHi[nt][0], bHi[nt][1], bh2);
                uint32_t bl2 = smem_u32(vL + (nw + nt * 8 + brow) * APAD + kk + bcol0);
                LDSM_X2(bLo[nt][0], bLo[nt][1], bl2);
            }
#pragma unroll
            for (int mt = 0; mt < 2; mt++)
#pragma unroll
                for (int nt = 0; nt < 4; nt++) {
                    mma16816(acc[mt][nt], aHi[mt], bHi[nt]);
                    mma16816(acc[mt][nt], aHi[mt], bLo[nt]);
                    mma16816(acc[mt][nt], aLo[mt], bHi[nt]);
                }
        }
        __syncthreads();
        if (c + 2 < NC) { load_stage(st, (c + 2) * 32); CP_COMMIT(); }
    }

#pragma unroll
    for (int mt = 0; mt < 2; mt++) {
        int s = m0 + mw + mt * 16 + (lane >> 2);
#pragma unroll
        for (int nt = 0; nt < 4; nt++) {
            int d = nw + nt * 8 + (lane & 3) * 2;
            size_t o1 = ((size_t)(b * SEQ + s)) * INNER + h * DKV + d;
            size_t o2 = ((size_t)(b * SEQ + s + 8)) * INNER + h * DKV + d;
            uint32_t hi, lo;
            split2(acc[mt][nt][0], acc[mt][nt][1], hi, lo);
            *(uint32_t*)&g_chi[o1] = hi; *(uint32_t*)&g_clo[o1] = lo;
            split2(acc[mt][nt][2], acc[mt][nt][3], hi, lo);
            *(uint32_t*)&g_chi[o2] = hi; *(uint32_t*)&g_clo[o2] = lo;
        }
    }
}

// ---------------- launch ----------------
extern "C" void kernel_launch(void* const* d_in, const int* in_sizes, int n_in,
                              void* d_out, int out_size) {
    const float* x  = (const float*)d_in[0];
    const float* Wq = (const float*)d_in[1];
    const float* bq = (const float*)d_in[2];
    const float* Wk = (const float*)d_in[3];
    const float* bk = (const float*)d_in[4];
    const float* Wv = (const float*)d_in[5];
    const float* bv = (const float*)d_in[6];
    const float* Wo = (const float*)d_in[7];
    const float* bo = (const float*)d_in[8];
    const float* rel_table = (const float*)d_in[9];
    const unsigned char* mask = (const unsigned char*)d_in[10];

    float* out = (float*)d_out;
    float* wts = out + (size_t)BSZ * SEQ * DMODEL;
    float* pb  = wts + (size_t)BSZ * NH * SEQ * SEQ;

    __nv_bfloat16 *pxhi, *pxlo, *pwhi, *pwlo, *pchi, *pclo;
    __nv_bfloat16 *pqhi, *pqlo, *pkhi, *pklo, *pvhi, *pvlo;
    cudaGetSymbolAddress((void**)&pxhi, g_xhi);
    cudaGetSymbolAddress((void**)&pxlo, g_xlo);
    cudaGetSymbolAddress((void**)&pwhi, g_whi);
    cudaGetSymbolAddress((void**)&pwlo, g_wlo);
    cudaGetSymbolAddress((void**)&pchi, g_chi);
    cudaGetSymbolAddress((void**)&pclo, g_clo);
    cudaGetSymbolAddress((void**)&pqhi, g_qhi);
    cudaGetSymbolAddress((void**)&pqlo, g_qlo);
    cudaGetSymbolAddress((void**)&pkhi, g_khi);
    cudaGetSymbolAddress((void**)&pklo, g_klo);
    cudaGetSymbolAddress((void**)&pvhi, g_vhi);
    cudaGetSymbolAddress((void**)&pvlo, g_vlo);

    cudaFuncSetAttribute(mma_gemm_kernel,
                         cudaFuncAttributeMaxDynamicSharedMemorySize, GEMM_SMEM);
    cudaFuncSetAttribute(qk_mma_kernel,
                         cudaFuncAttributeMaxDynamicSharedMemorySize, QK_SMEM);
    cudaFuncSetAttribute(wv_mma_kernel,
                         cudaFuncAttributeMaxDynamicSharedMemorySize, WV_SMEM);

    const size_t WSTRIDE = (size_t)DMODEL * INNER;

    maskprep_kernel<<<1, 1024>>>(mask);
    biasfill_kernel<<<256, 256>>>(rel_table);

    cvt_split_kernel<<<(MTOT * DMODEL) / 1024, 256>>>(x, pxhi, pxlo);
    dim3 tg(32, 32);
    transpose_split_kernel<<<tg, 256>>>(Wq, pwhi + 0 * WSTRIDE, pwlo + 0 * WSTRIDE);
    transpose_split_kernel<<<tg, 256>>>(Wk, pwhi + 1 * WSTRIDE, pwlo + 1 * WSTRIDE);
    transpose_split_kernel<<<tg, 256>>>(Wv, pwhi + 2 * WSTRIDE, pwlo + 2 * WSTRIDE);
    transpose_split_kernel<<<tg, 256>>>(Wo, pwhi + 3 * WSTRIDE, pwlo + 3 * WSTRIDE);

    dim3 gg(INNER / 64, MTOT / 128);   // (16, 32)
    mma_gemm_kernel<<<gg, 256, GEMM_SMEM>>>(pxhi, pxlo, pwhi + 0 * WSTRIDE, pwlo + 0 * WSTRIDE, bq,
                                            nullptr, pqhi, pqlo, 1);
    mma_gemm_kernel<<<gg, 256, GEMM_SMEM>>>(pxhi, pxlo, pwhi + 1 * WSTRIDE, pwlo + 1 * WSTRIDE, bk,
                                            nullptr, pkhi, pklo, 1);
    mma_gemm_kernel<<<gg, 256, GEMM_SMEM>>>(pxhi, pxlo, pwhi + 2 * WSTRIDE, pwlo + 2 * WSTRIDE, bv,
                                            nullptr, pvhi, pvlo, 1);

    vtrans_kernel<<<dim3(SEQ / 32, DKV / 32, BSZ * NH), 256>>>();

    qk_mma_kernel<<<dim3(SEQ / 128, BSZ * NH), 256, QK_SMEM>>>(wts);

    softmax_kernel<<<BSZ * NH * SEQ, 256>>>(wts, pb);

    wv_mma_kernel<<<dim3(SEQ / 128, BSZ * NH), 256, WV_SMEM>>>(wts);

    mma_gemm_kernel<<<gg, 256, GEMM_SMEM>>>(pchi, pclo, pwhi + 3 * WSTRIDE, pwlo + 3 * WSTRIDE, bo,
                                            out, nullptr, nullptr, 0);
}

// round 12
// speedup vs baseline: 2.2550x; 1.0344x over previous
#include <cuda_runtime.h>
#include <cuda_bf16.h>
#include <math.h>
#include <stdint.h>

#define BSZ 2
#define SEQ 2048
#define NH 16
#define DKV 64
#define DMODEL 1024
#define INNER 1024
#define MTOT (BSZ * SEQ)   // 4096
#define NHSD (BSZ * NH * SEQ * DKV)   // 4194304

// ---------------- scratch (static device memory; no allocations) ----------------
__device__ float g_bias[NH * 4096];
__device__ float g_maskf[BSZ * SEQ];
__device__ __nv_bfloat16 g_xhi[MTOT * DMODEL];
__device__ __nv_bfloat16 g_xlo[MTOT * DMODEL];
__device__ __nv_bfloat16 g_whi[4u * DMODEL * INNER];   // [n][k]; 0=Wq 1=Wk 2=Wv 3=Wo (contiguous)
__device__ __nv_bfloat16 g_wlo[4u * DMODEL * INNER];
__device__ __nv_bfloat16 g_qkvhi[2 * NHSD];            // 0:+NHSD = Q, NHSD..2N = K  (b,h,s,d)
__device__ __nv_bfloat16 g_qkvlo[2 * NHSD];
__device__ __nv_bfloat16 g_vthi[NHSD];                 // V transposed (b,h,d,s)
__device__ __nv_bfloat16 g_vtlo[NHSD];
__device__ __nv_bfloat16 g_chi[MTOT * INNER];          // (b,s,inner)
__device__ __nv_bfloat16 g_clo[MTOT * INNER];

// ---------------- PTX helpers ----------------
__device__ __forceinline__ uint32_t smem_u32(const void* p) {
    uint32_t a;
    asm("{ .reg .u64 t; cvta.to.shared.u64 t, %1; cvt.u32.u64 %0, t; }" : "=r"(a) : "l"(p));
    return a;
}
#define LDSM_X4(r0, r1, r2, r3, addr) \
    asm volatile("ldmatrix.sync.aligned.m8n8.x4.shared.b16 {%0,%1,%2,%3}, [%4];" \
                 : "=r"(r0), "=r"(r1), "=r"(r2), "=r"(r3) : "r"(addr))
#define LDSM_X2(r0, r1, addr) \
    asm volatile("ldmatrix.sync.aligned.m8n8.x2.shared.b16 {%0,%1}, [%2];" \
                 : "=r"(r0), "=r"(r1) : "r"(addr))
#define CP_ASYNC16(dst, src) \
    asm volatile("cp.async.cg.shared.global [%0], [%1], 16;" :: "r"(dst), "l"(src))
#define CP_COMMIT() asm volatile("cp.async.commit_group;" ::: "memory")
#define CP_WAIT0()  asm volatile("cp.async.wait_group 0;" ::: "memory")
#define CP_WAIT1()  asm volatile("cp.async.wait_group 1;" ::: "memory")
#define CP_WAIT2()  asm volatile("cp.async.wait_group 2;" ::: "memory")

__device__ __forceinline__ void mma16816(float* c, const uint32_t* a, const uint32_t* b) {
    asm volatile("mma.sync.aligned.m16n8k16.row.col.f32.bf16.bf16.f32 "
                 "{%0,%1,%2,%3}, {%4,%5,%6,%7}, {%8,%9}, {%0,%1,%2,%3};"
                 : "+f"(c[0]), "+f"(c[1]), "+f"(c[2]), "+f"(c[3])
                 : "r"(a[0]), "r"(a[1]), "r"(a[2]), "r"(a[3]), "r"(b[0]), "r"(b[1]));
}

__device__ __forceinline__ void split2(float v0, float v1, uint32_t& hi, uint32_t& lo) {
    __nv_bfloat16 h0 = __float2bfloat16(v0), h1 = __float2bfloat16(v1);
    __nv_bfloat16 l0 = __float2bfloat16(v0 - __bfloat162float(h0));
    __nv_bfloat16 l1 = __float2bfloat16(v1 - __bfloat162float(h1));
    hi = (uint32_t)__bfloat16_as_ushort(h0) | ((uint32_t)__bfloat16_as_ushort(h1) << 16);
    lo = (uint32_t)__bfloat16_as_ushort(l0) | ((uint32_t)__bfloat16_as_ushort(l1) << 16);
}
__device__ __forceinline__ void split1(float v, __nv_bfloat16& h, __nv_bfloat16& l) {
    h = __float2bfloat16(v);
    l = __float2bfloat16(v - __bfloat162float(h));
}

// ---------------- mask preprocessing (bool stored as int32) ----------------
__global__ void maskprep_kernel(const unsigned char* __restrict__ mraw) {
    __shared__ int s_nonzero;
    const int tid = threadIdx.x;
    if (tid == 0) s_nonzero = 0;
    __syncthreads();
    int cnt = 0;
    for (int i = tid; i < BSZ * SEQ; i += 1024)
        if ((i & 3) && mraw[i]) cnt++;
    if (cnt) atomicAdd(&s_nonzero, cnt);
    __syncthreads();
    const bool is_u8 = (s_nonzero > 0);
    const int* mi = (const int*)mraw;
    for (int i = tid; i < BSZ * SEQ; i += 1024) {
        int flag = is_u8 ? (int)mraw[i] : mi[i];
        g_maskf[i] = flag ? -INFINITY : 0.0f;
    }
}

// ---------------- T5 relative-position bucket ----------------
__device__ __forceinline__ int rel_bucket(int delta) {
    int ret = (delta > 0) ? 32 : 0;
    int n = (delta < 0) ? -delta : delta;
    if (n < 16) return ret + n;
    float t = logf((float)n / 16.0f);
    t = t / 1.1394342831883648f;
    t = t * 16.0f;
    int large = 16 + (int)t;
    if (large > 31) large = 31;
    return ret + large;
}

__global__ void biasfill_kernel(const float* __restrict__ rel_table) {
    int idx = blockIdx.x * 256 + threadIdx.x;
    int h = idx >> 12;
    int dd = idx & 4095;
    int delta = dd - (SEQ - 1);
    if (dd >= 2 * SEQ - 1) delta = 0;
    g_bias[idx] = rel_table[rel_bucket(delta) * NH + h];
}

// ---------------- f32 -> bf16 hi/lo split ----------------
__global__ void cvt_split_kernel(const float* __restrict__ src,
                                 __nv_bfloat16* __restrict__ dhi,
                                 __nv_bfloat16* __restrict__ dlo) {
    size_t i = ((size_t)blockIdx.x * 256 + threadIdx.x) * 4;
    float4 v = *(const float4*)(src + i);
    uint2 H, L;
    split2(v.x, v.y, H.x, L.x);
    split2(v.z, v.w, H.y, L.y);
    *(uint2*)(dhi + i) = H;
    *(uint2*)(dlo + i) = L;
}

// ---------------- all 4 weights: [K][N] f32 -> [N][K] bf16 hi/lo, one launch ----------------
__global__ void transpose_split_kernel(const float* __restrict__ w0,
                                       const float* __restrict__ w1,
                                       const float* __restrict__ w2,
                                       const float* __restrict__ w3) {
    __shared__ float t[32][33];
    const int z = blockIdx.z;
    const float* src = (z == 0) ? w0 : (z == 1) ? w1 : (z == 2) ? w2 : w3;
    __nv_bfloat16* dhi = g_whi + (size_t)z * DMODEL * INNER;
    __nv_bfloat16* dlo = g_wlo + (size_t)z * DMODEL * INNER;
    int tx = threadIdx.x & 31, ty = threadIdx.x >> 5;
    int n0 = blockIdx.x * 32, k0 = blockIdx.y * 32;
#pragma unroll
    for (int j = 0; j < 32; j += 8)
        t[ty + j][tx] = src[(size_t)(k0 + ty + j) * INNER + n0 + tx];
    __syncthreads();
#pragma unroll
    for (int j = 0; j < 32; j += 8) {
        float v = t[tx][ty + j];
        int n = n0 + ty + j, k = k0 + tx;
        __nv_bfloat16 h = __float2bfloat16(v);
        dhi[(size_t)n * DMODEL + k] = h;
        dlo[(size_t)n * DMODEL + k] = __float2bfloat16(v - __bfloat162float(h));
    }
}

// ---------------- 3-stage pipelined mma.sync GEMM ----------------
// mode 1: A=x, B=concat(WqT,WkT,WvT) N=3072; epilogue -> Q/K (b,h,s,d) hi/lo, V transposed
// mode 0: A=ctx hi/lo, B=WoT N=1024; epilogue -> flat f32 out + bo
#define APAD 40
#define GA_ELE (2 * 128 * APAD)   // A elems per stage (both halves)
#define GB_ELE (2 * 64 * APAD)
#define GEMM_SMEM ((3 * (GA_ELE + GB_ELE)) * 2)   // bytes (3 stages)

__global__ __launch_bounds__(256) void mma_gemm_kernel(
    const __nv_bfloat16* __restrict__ Ahi, const __nv_bfloat16* __restrict__ Alo,
    const __nv_bfloat16* __restrict__ Bhi, const __nv_bfloat16* __restrict__ Blo,
    const float* __restrict__ bias0, const float* __restrict__ bias1,
    const float* __restrict__ bias2, float* __restrict__ C, int mode)
{
    extern __shared__ char gsm_raw[];
    __nv_bfloat16* sA = (__nv_bfloat16*)gsm_raw;            // [st][half][128][APAD]
    __nv_bfloat16* sB = sA + 3 * GA_ELE;                    // [st][half][64][APAD]

    const int tid = threadIdx.x;
    const int wid = tid >> 5, lane = tid & 31;
    const int m0 = blockIdx.y * 128;
    const int n0b = blockIdx.x * 64;
    const int mw = (wid & 3) * 32;
    const int nw = (wid >> 2) * 32;

    float acc[2][4][4];
#pragma unroll
    for (int mt = 0; mt < 2; mt++)
#pragma unroll
        for (int nt = 0; nt < 4; nt++)
#pragma unroll
            for (int i = 0; i < 4; i++) acc[mt][nt][i] = 0.f;

    const int arow = lane & 15;
    const int acol0 = (lane >> 4) << 3;
    const int brow = lane & 7;
    const int bcol0 = ((lane >> 3) & 1) << 3;

    auto load_stage = [&](int st, int k0) {
#pragma unroll
        for (int h = 0; h < 2; h++) {
            const __nv_bfloat16* as = h ? Alo : Ahi;
#pragma unroll
            for (int it = 0; it < 2; it++) {
                int idx = tid + it * 256;
                int r = idx >> 2, seg = idx & 3;
                uint32_t dst = smem_u32(sA + ((st * 2 + h) * 128 + r) * APAD + seg * 8);
                CP_ASYNC16(dst, as + (size_t)(m0 + r) * 1024 + k0 + seg * 8);
            }
            const __nv_bfloat16* bs = h ? Blo : Bhi;
            {
                int r = tid >> 2, seg = tid & 3;
                uint32_t dst = smem_u32(sB + ((st * 2 + h) * 64 + r) * APAD + seg * 8);
                CP_ASYNC16(dst, bs + (size_t)(n0b + r) * 1024 + k0 + seg * 8);
            }
        }
    };

    load_stage(0, 0);  CP_COMMIT();
    load_stage(1, 32); CP_COMMIT();
    load_stage(2, 64); CP_COMMIT();

    const int NC = 1024 / 32;
    for (int c = 0; c < NC; c++) {
        CP_WAIT2();
        __syncthreads();
        const int st = c % 3;
        __nv_bfloat16* aH = sA + (st * 2 + 0) * 128 * APAD;
        __nv_bfloat16* aL = sA + (st * 2 + 1) * 128 * APAD;
        __nv_bfloat16* bH = sB + (st * 2 + 0) * 64 * APAD;
        __nv_bfloat16* bL = sB + (st * 2 + 1) * 64 * APAD;
#pragma unroll
        for (int kk = 0; kk < 32; kk += 16) {
            uint32_t aHi[2][4], aLo[2][4], bHi[4][2], bLo[4][2];
#pragma unroll
            for (int mt = 0; mt < 2; mt++) {
                uint32_t ah = smem_u32(aH + (mw + mt * 16 + arow) * APAD + kk + acol0);
                LDSM_X4(aHi[mt][0], aHi[mt][1], aHi[mt][2], aHi[mt][3], ah);
                uint32_t al = smem_u32(aL + (mw + mt * 16 + arow) * APAD + kk + acol0);
                LDSM_X4(aLo[mt][0], aLo[mt][1], aLo[mt][2], aLo[mt][3], al);
            }
#pragma unroll
            for (int nt = 0; nt < 4; nt++) {
                uint32_t bh = smem_u32(bH + (nw + nt * 8 + brow) * APAD + kk + bcol0);
                LDSM_X2(bHi[nt][0], bHi[nt][1], bh);
                uint32_t bl = smem_u32(bL + (nw + nt * 8 + brow) * APAD + kk + bcol0);
                LDSM_X2(bLo[nt][0], bLo[nt][1], bl);
            }
#pragma unroll
            for (int mt = 0; mt < 2; mt++)
#pragma unroll
                for (int nt = 0; nt < 4; nt++) {
                    mma16816(acc[mt][nt], aHi[mt], bHi[nt]);
                    mma16816(acc[mt][nt], aHi[mt], bLo[nt]);
                    mma16816(acc[mt][nt], aLo[mt], bHi[nt]);
                }
        }
        __syncthreads();
        if (c + 3 < NC) load_stage(st, (c + 3) * 32);
        CP_COMMIT();
    }

    const int proj = n0b >> 10;   // 0,1,2 (mode 1); 0 (mode 0)
    const float* bias = (mode == 0) ? bias0
                        : (proj == 0 ? bias0 : (proj == 1 ? bias1 : bias2));

#pragma unroll
    for (int mt = 0; mt < 2; mt++) {
        int r = m0 + mw + mt * 16 + (lane >> 2);
#pragma unroll
        for (int nt = 0; nt < 4; nt++) {
            int n = n0b + nw + nt * 8 + (lane & 3) * 2;
            int nn = n & 1023;
            float v0 = acc[mt][nt][0] + bias[nn], v1 = acc[mt][nt][1] + bias[nn + 1];
            float v2 = acc[mt][nt][2] + bias[nn], v3 = acc[mt][nt][3] + bias[nn + 1];
            if (mode == 0) {
                *(float2*)&C[(size_t)r * 1024 + n] = make_float2(v0, v1);
                *(float2*)&C[(size_t)(r + 8) * 1024 + n] = make_float2(v2, v3);
            } else {
                int h = nn >> 6, d = nn & 63;
                int b = r >> 11, s = r & (SEQ - 1);
                int b2 = (r + 8) >> 11, s2 = (r + 8) & (SEQ - 1);
                if (proj < 2) {
                    size_t base = (size_t)proj * NHSD;
                    size_t o1 = base + (((size_t)(b * NH + h)) * SEQ + s) * DKV + d;
                    size_t o2 = base + (((size_t)(b2 * NH + h)) * SEQ + s2) * DKV + d;
                    uint32_t hi, lo;
                    split2(v0, v1, hi, lo);
                    *(uint32_t*)&g_qkvhi[o1] = hi; *(uint32_t*)&g_qkvlo[o1] = lo;
                    split2(v2, v3, hi, lo);
                    *(uint32_t*)&g_qkvhi[o2] = hi; *(uint32_t*)&g_qkvlo[o2] = lo;
                } else {
                    // V: write transposed (b,h,d,s)
                    size_t vb1 = ((size_t)(b * NH + h)) * DKV * SEQ;
                    size_t vb2 = ((size_t)(b2 * NH + h)) * DKV * SEQ;
                    __nv_bfloat16 hh, ll;
                    split1(v0, hh, ll);
                    g_vthi[vb1 + (size_t)d * SEQ + s] = hh; g_vtlo[vb1 + (size_t)d * SEQ + s] = ll;
                    split1(v1, hh, ll);
                    g_vthi[vb1 + (size_t)(d + 1) * SEQ + s] = hh; g_vtlo[vb1 + (size_t)(d + 1) * SEQ + s] = ll;
                    split1(v2, hh, ll);
                    g_vthi[vb2 + (size_t)d * SEQ + s2] = hh; g_vtlo[vb2 + (size_t)d * SEQ + s2] = ll;
                    split1(v3, hh, ll);
                    g_vthi[vb2 + (size_t)(d + 1) * SEQ + s2] = hh; g_vtlo[vb2 + (size_t)(d + 1) * SEQ + s2] = ll;
                }
            }
        }
    }
}

// ---------------- scores = Q K^T, pipelined hi/lo ----------------
#define QKPAD 72
#define QK_TILE (2 * 128 * QKPAD)                 // elems per (half-pair) tile
#define QK_SMEM ((QK_TILE * 3) * 2)               // bytes: Q + 2 K stages

__global__ __launch_bounds__(256) void qk_mma_kernel(float* __restrict__ wts) {
    extern __shared__ char qsm_raw[];
    __nv_bfloat16* sQ = (__nv_bfloat16*)qsm_raw;  // [half][128][QKPAD]
    __nv_bfloat16* sK = sQ + QK_TILE;             // [st][half][128][QKPAD]

    const int tid = threadIdx.x, wid = tid >> 5, lane = tid & 31;
    const int q0 = blockIdx.x * 128;
    const int bh = blockIdx.y;
    const size_t base = (size_t)bh * SEQ * DKV;
    float* sp = wts + (size_t)bh * SEQ * SEQ;

    const __nv_bfloat16* qhi = g_qkvhi;
    const __nv_bfloat16* qlo = g_qkvlo;
    const __nv_bfloat16* khi = g_qkvhi + NHSD;
    const __nv_bfloat16* klo = g_qkvlo + NHSD;

    const int mw = (wid & 3) * 32;
    const int nw = (wid >> 2) * 64;
    const int arow = lane & 15;
    const int acol0 = (lane >> 4) << 3;
    const int brow = lane & 7;
    const int bcol0 = ((lane >> 3) & 1) << 3;

    // Q tile (persistent, synchronous)
#pragma unroll
    for (int it = 0; it < 4; it++) {
        int i = tid + it * 256;
        int r = i >> 3, seg = i & 7;
        size_t o = base + (size_t)(q0 + r) * DKV + seg * 8;
        *(uint4*)(sQ + r * QKPAD + seg * 8) = *(const uint4*)(qhi + o);
        *(uint4*)(sQ + (128 + r) * QKPAD + seg * 8) = *(const uint4*)(qlo + o);
    }

    auto load_k = [&](int st, int kt) {
#pragma unroll
        for (int h = 0; h < 2; h++) {
            const __nv_bfloat16* ks = h ? klo : khi;
#pragma unroll
            for (int it = 0; it < 4; it++) {
                int i = tid + it * 256;
                int r = i >> 3, seg = i & 7;
                uint32_t dst = smem_u32(sK + ((st * 2 + h) * 128 + r) * QKPAD + seg * 8);
                CP_ASYNC16(dst, ks + base + (size_t)(kt * 128 + r) * DKV + seg * 8);
            }
        }
    };

    load_k(0, 0); CP_COMMIT();
    load_k(1, 1); CP_COMMIT();

    for (int kt = 0; kt < 16; kt++) {
        if (kt == 15) CP_WAIT0(); else CP_WAIT1();
        __syncthreads();
        const int st = kt & 1;
        __nv_bfloat16* kH = sK + (st * 2 + 0) * 128 * QKPAD;
        __nv_bfloat16* kL = sK + (st * 2 + 1) * 128 * QKPAD;

        float acc[2][8][4];
#pragma unroll
        for (int mt = 0; mt < 2; mt++)
#pragma unroll
            for (int nt = 0; nt < 8; nt++)
#pragma unroll
                for (int i = 0; i < 4; i++) acc[mt][nt][i] = 0.f;

#pragma unroll
        for (int kk = 0; kk < 64; kk += 16) {
            uint32_t aHi[2][4], aLo[2][4];
#pragma unroll
            for (int mt = 0; mt < 2; mt++) {
                uint32_t ah = smem_u32(sQ + (mw + mt * 16 + arow) * QKPAD + kk + acol0);
                LDSM_X4(aHi[mt][0], aHi[mt][1], aHi[mt][2], aHi[mt][3], ah);
                uint32_t al = smem_u32(sQ + (128 + mw + mt * 16 + arow) * QKPAD + kk + acol0);
                LDSM_X4(aLo[mt][0], aLo[mt][1], aLo[mt][2], aLo[mt][3], al);
            }
#pragma unroll
            for (int g = 0; g < 2; g++) {
                uint32_t bHi[4][2], bLo[4][2];
#pragma unroll
                for (int j = 0; j < 4; j++) {
                    int nt = g * 4 + j;
                    uint32_t bh2 = smem_u32(kH + (nw + nt * 8 + brow) * QKPAD + kk + bcol0);
                    LDSM_X2(bHi[j][0], bHi[j][1], bh2);
                    uint32_t bl2 = smem_u32(kL + (nw + nt * 8 + brow) * QKPAD + kk + bcol0);
                    LDSM_X2(bLo[j][0], bLo[j][1], bl2);
                }
#pragma unroll
                for (int mt = 0; mt < 2; mt++)
#pragma unroll
                    for (int j = 0; j < 4; j++) {
                        int nt = g * 4 + j;
                        mma16816(acc[mt][nt], aHi[mt], bHi[j]);
                        mma16816(acc[mt][nt], aHi[mt], bLo[j]);
                        mma16816(acc[mt][nt], aLo[mt], bHi[j]);
                    }
            }
        }

#pragma unroll
        for (int mt = 0; mt < 2; mt++) {
            int r = q0 + mw + mt * 16 + (lane >> 2);
            float* row0 = sp + (size_t)r * SEQ + kt * 128;
            float* row1 = row0 + 8 * SEQ;
#pragma unroll
            for (int nt = 0; nt < 8; nt++) {
                int c = nw + nt * 8 + (lane & 3) * 2;
                *(float2*)&row0[c] = make_float2(acc[mt][nt][0], acc[mt][nt][1]);
                *(float2*)&row1[c] = make_float2(acc[mt][nt][2], acc[mt][nt][3]);
            }
        }
        __syncthreads();
        if (kt + 2 < 16) { load_k(st, kt + 2); CP_COMMIT(); }
    }
}

// ---------------- softmax in-place (vectorized); emits pos_bias from b==0 ----------------
__global__ __launch_bounds__(256) void softmax_kernel(float* __restrict__ wts,
                                                      float* __restrict__ pb)
{
    const int row = blockIdx.x;
    const int q = row & (SEQ - 1);
    const int bh = row >> 11;
    const int h = bh & 15, b = bh >> 4;
    float* wp = wts + (size_t)row * SEQ;
    const float* bias_h = g_bias + (h << 12) + (SEQ - 1) - q;
    const float* mrow = g_maskf + b * SEQ;
    float* pbrow = pb + ((size_t)(h * SEQ + q)) * SEQ;
    const int tid = threadIdx.x;
    const int k0 = tid * 8;

    __shared__ float sm[8], ss[8];
    float v[8], bvv[8];
    float4 s0 = *(float4*)&wp[k0], s1 = *(float4*)&wp[k0 + 4];
    float4 mk0 = *(float4*)&mrow[k0], mk1 = *(float4*)&mrow[k0 + 4];
    float sv[8] = {s0.x, s0.y, s0.z, s0.w, s1.x, s1.y, s1.z, s1.w};
    float mv[8] = {mk0.x, mk0.y, mk0.z, mk0.w, mk1.x, mk1.y, mk1.z, mk1.w};
    float mx = -INFINITY;
#pragma unroll
    for (int i = 0; i < 8; i++) {
        bvv[i] = bias_h[k0 + i];
        float val = sv[i] + bvv[i] + mv[i];
        v[i] = val;
        mx = fmaxf(mx, val);
    }
    if (b == 0) {
        *(float4*)&pbrow[k0] = make_float4(bvv[0], bvv[1], bvv[2], bvv[3]);
        *(float4*)&pbrow[k0 + 4] = make_float4(bvv[4], bvv[5], bvv[6], bvv[7]);
    }
    for (int o = 16; o; o >>= 1) mx = fmaxf(mx, __shfl_xor_sync(0xffffffffu, mx, o));
    if ((tid & 31) == 0) sm[tid >> 5] = mx;
    __syncthreads();
    mx = sm[0];
#pragma unroll
    for (int w = 1; w < 8; w++) mx = fmaxf(mx, sm[w]);

    float sum = 0.f;
#pragma unroll
    for (int i = 0; i < 8; i++) { v[i] = __expf(v[i] - mx); sum += v[i]; }
    for (int o = 16; o; o >>= 1) sum += __shfl_xor_sync(0xffffffffu, sum, o);
    if ((tid & 31) == 0) ss[tid >> 5] = sum;
    __syncthreads();
    sum = 0.f;
#pragma unroll
    for (int w = 0; w < 8; w++) sum += ss[w];
    float inv = 1.0f / sum;
    *(float4*)&wp[k0] = make_float4(v[0] * inv, v[1] * inv, v[2] * inv, v[3] * inv);
    *(float4*)&wp[k0 + 4] = make_float4(v[4] * inv, v[5] * inv, v[6] * inv, v[7] * inv);
}

// ---------------- ctx = weights @ V, pipelined hi/lo ----------------
#define WV_W_ELE (2 * 128 * APAD)                 // bf16 elems
#define WV_V_ELE (2 * 64 * APAD)                  // per stage
#define WV_SMEM (WV_W_ELE * 2 + 2 * WV_V_ELE * 2 + 2 * 128 * 32 * 4)

__global__ __launch_bounds__(256) void wv_mma_kernel(const float* __restrict__ wts) {
    extern __shared__ char wsm_raw[];
    __nv_bfloat16* sW = (__nv_bfloat16*)wsm_raw;             // [half][128][APAD]
    __nv_bfloat16* sV = sW + WV_W_ELE;                        // [st][half][64][APAD]
    float* sWraw = (float*)(sV + 2 * WV_V_ELE);               // [st][128][32]

    const int tid = threadIdx.x, wid = tid >> 5, lane = tid & 31;
    const int m0 = blockIdx.x * 128;
    const int bh = blockIdx.y;
    const int b = bh >> 4, h = bh & 15;
    const float* wp = wts + (size_t)bh * SEQ * SEQ;
    const __nv_bfloat16* vh = g_vthi + (size_t)bh * DKV * SEQ;
    const __nv_bfloat16* vl = g_vtlo + (size_t)bh * DKV * SEQ;

    const int mw = (wid & 3) * 32;
    const int nw = (wid >> 2) * 32;
    const int arow = lane & 15;
    const int acol0 = (lane >> 4) << 3;
    const int brow = lane & 7;
    const int bcol0 = ((lane >> 3) & 1) << 3;

    float acc[2][4][4];
#pragma unroll
    for (int mt = 0; mt < 2; mt++)
#pragma unroll
        for (int nt = 0; nt < 4; nt++)
#pragma unroll
            for (int i = 0; i < 4; i++) acc[mt][nt][i] = 0.f;

    auto load_stage = [&](int st, int k0) {
#pragma unroll
        for (int hh = 0; hh < 2; hh++) {
            const __nv_bfloat16* vs = hh ? vl : vh;
            int r = tid >> 2, seg = tid & 3;
            uint32_t dst = smem_u32(sV + ((st * 2 + hh) * 64 + r) * APAD + seg * 8);
            CP_ASYNC16(dst, vs + (size_t)r * SEQ + k0 + seg * 8);
        }
#pragma unroll
        for (int it = 0; it < 4; it++) {
            int i = tid + it * 256;
            int r = i >> 3, seg = i & 7;
            uint32_t dst = smem_u32(sWraw + (st * 128 + r) * 32 + seg * 4);
            CP_ASYNC16(dst, wp + (size_t)(m0 + r) * SEQ + k0 + seg * 4);
        }
    };

    load_stage(0, 0);  CP_COMMIT();
    load_stage(1, 32); CP_COMMIT();

    const int NC = SEQ / 32;
    for (int c = 0; c < NC; c++) {
        if (c == NC - 1) CP_WAIT0(); else CP_WAIT1();
        __syncthreads();
        const int st = c & 1;
#pragma unroll
        for (int it = 0; it < 4; it++) {
            int i = tid + it * 256;
            int r = i >> 3, seg = i & 7;
            float4 v = *(float4*)(sWraw + (st * 128 + r) * 32 + seg * 4);
            uint2 H, L;
            split2(v.x, v.y, H.x, L.x);
            split2(v.z, v.w, H.y, L.y);
            *(uint2*)(sW + r * APAD + seg * 4) = H;
            *(uint2*)(sW + (128 + r) * APAD + seg * 4) = L;
        }
        __syncthreads();

        __nv_bfloat16* vH = sV + (st * 2 + 0) * 64 * APAD;
        __nv_bfloat16* vL = sV + (st * 2 + 1) * 64 * APAD;
#pragma unroll
        for (int kk = 0; kk < 32; kk += 16) {
            uint32_t aHi[2][4], aLo[2][4], bHi[4][2], bLo[4][2];
#pragma unroll
            for (int mt = 0; mt < 2; mt++) {
                uint32_t ah = smem_u32(sW + (mw + mt * 16 + arow) * APAD + kk + acol0);
                LDSM_X4(aHi[mt][0], aHi[mt][1], aHi[mt][2], aHi[mt][3], ah);
                uint32_t al = smem_u32(sW + (128 + mw + mt * 16 + arow) * APAD + kk + acol0);
                LDSM_X4(aLo[mt][0], aLo[mt][1], aLo[mt][2], aLo[mt][3], al);
            }
#pragma unroll
            for (int nt = 0; nt < 4; nt++) {
                uint32_t bh2 = smem_u32(vH + (nw + nt * 8 + brow) * APAD + kk + bcol0);
                LDSM_X2(bHi[nt][0], bHi[nt][1], bh2);
                uint32_t bl2 = smem_u32(vL + (nw + nt * 8 + brow) * APAD + kk + bcol0);
                LDSM_X2(bLo[nt][0], bLo[nt][1], bl2);
            }
#pragma unroll
            for (int mt = 0; mt < 2; mt++)
#pragma unroll
                for (int nt = 0; nt < 4; nt++) {
                    mma16816(acc[mt][nt], aHi[mt], bHi[nt]);
                    mma16816(acc[mt][nt], aHi[mt], bLo[nt]);
                    mma16816(acc[mt][nt], aLo[mt], bHi[nt]);
                }
        }
        __syncthreads();
        if (c + 2 < NC) { load_stage(st, (c + 2) * 32); CP_COMMIT(); }
    }

#pragma unroll
    for (int mt = 0; mt < 2; mt++) {
        int s = m0 + mw + mt * 16 + (lane >> 2);
#pragma unroll
        for (int nt = 0; nt < 4; nt++) {
            int d = nw + nt * 8 + (lane & 3) * 2;
            size_t o1 = ((size_t)(b * SEQ + s)) * INNER + h * DKV + d;
            size_t o2 = ((size_t)(b * SEQ + s + 8)) * INNER + h * DKV + d;
            uint32_t hi, lo;
            split2(acc[mt][nt][0], acc[mt][nt][1], hi, lo);
            *(uint32_t*)&g_chi[o1] = hi; *(uint32_t*)&g_clo[o1] = lo;
            split2(acc[mt][nt][2], acc[mt][nt][3], hi, lo);
            *(uint32_t*)&g_chi[o2] = hi; *(uint32_t*)&g_clo[o2] = lo;
        }
    }
}

// ---------------- launch ----------------
extern "C" void kernel_launch(void* const* d_in, const int* in_sizes, int n_in,
                              void* d_out, int out_size) {
    const float* x  = (const float*)d_in[0];
    const float* Wq = (const float*)d_in[1];
    const float* bq = (const float*)d_in[2];
    const float* Wk = (const float*)d_in[3];
    const float* bk = (const float*)d_in[4];
    const float* Wv = (const float*)d_in[5];
    const float* bv = (const float*)d_in[6];
    const float* Wo = (const float*)d_in[7];
    const float* bo = (const float*)d_in[8];
    const float* rel_table = (const float*)d_in[9];
    const unsigned char* mask = (const unsigned char*)d_in[10];

    float* out = (float*)d_out;
    float* wts = out + (size_t)BSZ * SEQ * DMODEL;
    float* pb  = wts + (size_t)BSZ * NH * SEQ * SEQ;

    __nv_bfloat16 *pxhi, *pxlo, *pwhi, *pwlo, *pchi, *pclo;
    cudaGetSymbolAddress((void**)&pxhi, g_xhi);
    cudaGetSymbolAddress((void**)&pxlo, g_xlo);
    cudaGetSymbolAddress((void**)&pwhi, g_whi);
    cudaGetSymbolAddress((void**)&pwlo, g_wlo);
    cudaGetSymbolAddress((void**)&pchi, g_chi);
    cudaGetSymbolAddress((void**)&pclo, g_clo);

    cudaFuncSetAttribute(mma_gemm_kernel,
                         cudaFuncAttributeMaxDynamicSharedMemorySize, GEMM_SMEM);
    cudaFuncSetAttribute(qk_mma_kernel,
                         cudaFuncAttributeMaxDynamicSharedMemorySize, QK_SMEM);
    cudaFuncSetAttribute(wv_mma_kernel,
                         cudaFuncAttributeMaxDynamicSharedMemorySize, WV_SMEM);

    const size_t WSTRIDE = (size_t)DMODEL * INNER;

    maskprep_kernel<<<1, 1024>>>(mask);                       // launch 1
    biasfill_kernel<<<256, 256>>>(rel_table);                 // launch 2
    cvt_split_kernel<<<(MTOT * DMODEL) / 1024, 256>>>(x, pxhi, pxlo);   // launch 3
    transpose_split_kernel<<<dim3(32, 32, 4), 256>>>(Wq, Wk, Wv, Wo);   // launch 4

    // fused QKV projection: N = 3072                         // launch 5
    mma_gemm_kernel<<<dim3(3 * INNER / 64, MTOT / 128), 256, GEMM_SMEM>>>(
        pxhi, pxlo, pwhi, pwlo, bq, bk, bv, nullptr, 1);

    qk_mma_kernel<<<dim3(SEQ / 128, BSZ * NH), 256, QK_SMEM>>>(wts);    // launch 6 (ncu)

    softmax_kernel<<<BSZ * NH * SEQ, 256>>>(wts, pb);

    wv_mma_kernel<<<dim3(SEQ / 128, BSZ * NH), 256, WV_SMEM>>>(wts);

    mma_gemm_kernel<<<dim3(INNER / 64, MTOT / 128), 256, GEMM_SMEM>>>(
        pchi, pclo, pwhi + 3 * WSTRIDE, pwlo + 3 * WSTRIDE, bo, bo, bo, out, 0);
}